// round 1
// baseline (speedup 1.0000x reference)
#include <cuda_runtime.h>

#define NMAX 50000
#define F 128
#define DEG 32

// Scratch buffers (device globals — no allocation allowed in kernel_launch).
__device__ float g_m1[NMAX * F];   // mean of neighbor feats
__device__ float g_h1[NMAX * F];   // layer-1 hidden
__device__ float g_m2[NMAX * F];   // mean of neighbor h1

// ---------------------------------------------------------------------------
// Gather-mean: dst[i] = mean_j src[neigh[node(i)][j]]  (width 128, warp/node)
// node(i) = batch ? batch[i] : i
// ---------------------------------------------------------------------------
__global__ __launch_bounds__(256)
void gather_mean128(const float* __restrict__ src,
                    const int* __restrict__ neigh,
                    const int* __restrict__ batch,
                    float* __restrict__ dst, int N)
{
    int w    = (blockIdx.x * blockDim.x + threadIdx.x) >> 5;
    int lane = threadIdx.x & 31;
    if (w >= N) return;
    int node  = batch ? batch[w] : w;
    int myidx = neigh[node * DEG + lane];   // one index per lane, coalesced

    float4 acc = make_float4(0.f, 0.f, 0.f, 0.f);
#pragma unroll
    for (int j = 0; j < DEG; ++j) {
        int nb = __shfl_sync(0xffffffffu, myidx, j);
        float4 v = __ldg(reinterpret_cast<const float4*>(src + (long)nb * F) + lane);
        acc.x += v.x; acc.y += v.y; acc.z += v.z; acc.w += v.w;
    }
    const float s = 1.0f / (float)DEG;
    acc.x *= s; acc.y *= s; acc.z *= s; acc.w *= s;
    reinterpret_cast<float4*>(dst + (long)w * F)[lane] = acc;
}

// ---------------------------------------------------------------------------
// Tiled GEMM on virtually-concatenated A = [A1 | A2] (each [N, F] row-major):
//   C[i][c] = act( sum_k A[i][k] * B[k][c] + bias[c] ),  k in [0, 2F)
// rowmap (if non-null) remaps the row index for the A1 half ONLY
// (layer 2: self rows go through batch; A2 = m2 is already per-output-row).
// LDB = true number of B columns (C leading dim); BN >= LDB (padded tiles).
// ---------------------------------------------------------------------------
template <int BM, int BN, int BK, int TM, int TN, int LDB, bool RELU>
__global__ __launch_bounds__((BM / TM) * (BN / TN))
void gemm_cat_kernel(const float* __restrict__ A1,
                     const float* __restrict__ A2,
                     const int*   __restrict__ rowmap,
                     const float* __restrict__ B,
                     const float* __restrict__ bias,
                     float* __restrict__ C, int N)
{
    constexpr int NT = (BM / TM) * (BN / TN);

    __shared__ float As[BM][BK + 1];   // +1 pad: conflict-free loads/stores
    __shared__ float Bs[BK][BN];

    const int tid     = threadIdx.x;
    const int rowBase = blockIdx.x * BM;

    const int tCol = tid % (BN / TN);
    const int tRow = tid / (BN / TN);

    // A-tile load mapping: thread -> (row group, k within tile)
    const int aRow0 = tid / BK;
    const int aCol  = tid % BK;
    constexpr int ASTRIDE = NT / BK;

    // B-tile load mapping
    const int bRow0 = tid / BN;
    const int bCol  = tid % BN;
    constexpr int BSTRIDE = NT / BN;

    float acc[TM][TN];
#pragma unroll
    for (int i = 0; i < TM; ++i)
#pragma unroll
        for (int j = 0; j < TN; ++j) acc[i][j] = 0.f;

    for (int k0 = 0; k0 < 2 * F; k0 += BK) {
        const bool  firstHalf = (k0 < F);
        const float* Asrc = firstHalf ? A1 : A2;
        const int    kOff = firstHalf ? k0 : (k0 - F);

        // Load A tile
#pragma unroll
        for (int r = 0; r < BM; r += ASTRIDE) {
            int row  = r + aRow0;
            int grow = rowBase + row;
            float v = 0.f;
            if (grow < N) {
                int gr = (rowmap && firstHalf) ? rowmap[grow] : grow;
                v = Asrc[(long)gr * F + kOff + aCol];
            }
            As[row][aCol] = v;
        }
        // Load B tile (guard cols beyond LDB with zeros)
#pragma unroll
        for (int r = 0; r < BK; r += BSTRIDE) {
            int row = r + bRow0;
            float v = 0.f;
            if (bCol < LDB) v = B[(long)(k0 + row) * LDB + bCol];
            Bs[row][bCol] = v;
        }
        __syncthreads();

#pragma unroll
        for (int k = 0; k < BK; ++k) {
            float regM[TM], regN[TN];
#pragma unroll
            for (int i = 0; i < TM; ++i) regM[i] = As[tRow * TM + i][k];
#pragma unroll
            for (int j = 0; j < TN; ++j) regN[j] = Bs[k][tCol * TN + j];
#pragma unroll
            for (int i = 0; i < TM; ++i)
#pragma unroll
                for (int j = 0; j < TN; ++j)
                    acc[i][j] += regM[i] * regN[j];
        }
        __syncthreads();
    }

    // Epilogue: bias (+relu), store only real columns/rows
#pragma unroll
    for (int i = 0; i < TM; ++i) {
        int grow = rowBase + tRow * TM + i;
        if (grow >= N) continue;
#pragma unroll
        for (int j = 0; j < TN; ++j) {
            int col = tCol * TN + j;
            if (col >= LDB) continue;
            float v = acc[i][j] + bias[col];
            if (RELU) v = fmaxf(v, 0.f);
            C[(long)grow * LDB + col] = v;
        }
    }
}

// ---------------------------------------------------------------------------
// Launch
// ---------------------------------------------------------------------------
extern "C" void kernel_launch(void* const* d_in, const int* in_sizes, int n_in,
                              void* d_out, int out_size)
{
    const float* feats = (const float*)d_in[0];
    const int*   neigh = (const int*)  d_in[1];
    const int*   batch = (const int*)  d_in[2];
    const float* W1    = (const float*)d_in[3];
    const float* b1    = (const float*)d_in[4];
    const float* W2    = (const float*)d_in[5];
    const float* b2    = (const float*)d_in[6];
    float*       out   = (float*)d_out;

    const int N = in_sizes[0] / F;   // 50000 nodes
    const int B = in_sizes[2];       // batch size (= N)

    float *m1, *h1, *m2;
    cudaGetSymbolAddress((void**)&m1, g_m1);
    cudaGetSymbolAddress((void**)&h1, g_h1);
    cudaGetSymbolAddress((void**)&m2, g_m2);

    // Layer 1: gather-mean of raw feats, then relu GEMM -> h1
    {
        int blocks = (N * 32 + 255) / 256;
        gather_mean128<<<blocks, 256>>>(feats, neigh, nullptr, m1, N);
        int gblocks = (N + 127) / 128;
        gemm_cat_kernel<128, 128, 16, 8, 8, 128, true>
            <<<gblocks, 256>>>(feats, m1, nullptr, W1, b1, h1, N);
    }
    // Layer 2: gather-mean of h1 (through batch), then GEMM -> out
    {
        int blocks = (B * 32 + 255) / 256;
        gather_mean128<<<blocks, 256>>>(h1, neigh, batch, m2, B);
        int gblocks = (B + 127) / 128;
        gemm_cat_kernel<128, 64, 16, 8, 4, 40, false>
            <<<gblocks, 256>>>(h1, m2, batch, W2, b2, out, B);
    }
}

// round 2
// speedup vs baseline: 1.1104x; 1.1104x over previous
#include <cuda_runtime.h>

#define NMAX 50000
#define F 128
#define DEG 32
#define L2OUT 40

typedef unsigned long long U64;

// Scratch (device globals — no allocation allowed).
__device__ float g_m1[NMAX * F];        // mean of neighbor feats
__device__ float g_h1[NMAX * F];        // layer-1 hidden
__device__ float g_p [NMAX * 2 * L2OUT]; // [p_self | p_nbr] projections

// ---------------- f32x2 packed-FMA helpers ----------------
__device__ __forceinline__ U64 dup2(float a) {
    U64 r; asm("mov.b64 %0, {%1, %1};" : "=l"(r) : "f"(a)); return r;
}
__device__ __forceinline__ void fma2(U64 &c, U64 a, U64 b) {
    asm("fma.rn.f32x2 %0, %1, %2, %0;" : "+l"(c) : "l"(a), "l"(b));
}
__device__ __forceinline__ float2 unpack2(U64 v) {
    float2 f; asm("mov.b64 {%0, %1}, %2;" : "=f"(f.x), "=f"(f.y) : "l"(v)); return f;
}

// ---------------------------------------------------------------------------
// Gather-mean width 128: dst[i] = mean_j src[neigh[i][j]]   (warp per node)
// ---------------------------------------------------------------------------
__global__ __launch_bounds__(256)
void gather_mean128(const float* __restrict__ src,
                    const int* __restrict__ neigh,
                    float* __restrict__ dst, int N)
{
    int w    = (blockIdx.x * blockDim.x + threadIdx.x) >> 5;
    int lane = threadIdx.x & 31;
    if (w >= N) return;
    int myidx = neigh[w * DEG + lane];

    float4 acc = make_float4(0.f, 0.f, 0.f, 0.f);
#pragma unroll
    for (int j = 0; j < DEG; ++j) {
        int nb = __shfl_sync(0xffffffffu, myidx, j);
        float4 v = __ldg(reinterpret_cast<const float4*>(src + (long)nb * F) + lane);
        acc.x += v.x; acc.y += v.y; acc.z += v.z; acc.w += v.w;
    }
    const float s = 1.0f / (float)DEG;
    acc.x *= s; acc.y *= s; acc.z *= s; acc.w *= s;
    reinterpret_cast<float4*>(dst + (long)w * F)[lane] = acc;
}

// ---------------------------------------------------------------------------
// Layer-1 GEMM: h1 = relu([feats | m1] @ W1 + b1)
// BM=64, BN=128, BK=16, TM=4, TN=8, 256 threads, f32x2 FMAs.
// ---------------------------------------------------------------------------
__global__ __launch_bounds__(256)
void gemm1_kernel(const float* __restrict__ A1,   // feats [N,128]
                  const float* __restrict__ A2,   // m1    [N,128]
                  const float* __restrict__ B,    // W1    [256,128]
                  const float* __restrict__ bias, // b1    [128]
                  float* __restrict__ C, int N)   // h1    [N,128]
{
    constexpr int BM = 64, BN = 128, BK = 16, TM = 4, TN = 8, NT = 256;

    __shared__ float As[BM][BK + 1];
    __shared__ float Bs[BK][BN];

    const int tid = threadIdx.x;
    const int rowBase = blockIdx.x * BM;
    const int tCol = tid & 15;        // 0..15  (BN/TN = 16)
    const int tRow = tid >> 4;        // 0..15  (BM/TM = 16)

    U64 acc[TM][TN / 2];
#pragma unroll
    for (int i = 0; i < TM; ++i)
#pragma unroll
        for (int j = 0; j < TN / 2; ++j) acc[i][j] = 0ull;

    for (int k0 = 0; k0 < 2 * F; k0 += BK) {
        const bool firstHalf = (k0 < F);
        const float* Asrc = firstHalf ? A1 : A2;
        const int kOff = firstHalf ? k0 : (k0 - F);

#pragma unroll
        for (int idx = tid; idx < BM * BK; idx += NT) {
            int row = idx / BK, col = idx % BK;
            int grow = rowBase + row;
            As[row][col] = (grow < N) ? Asrc[(long)grow * F + kOff + col] : 0.f;
        }
#pragma unroll
        for (int idx = tid; idx < BK * BN; idx += NT) {
            int row = idx / BN, col = idx % BN;
            Bs[row][col] = B[(long)(k0 + row) * BN + col];
        }
        __syncthreads();

#pragma unroll
        for (int k = 0; k < BK; ++k) {
            U64 regM[TM];
#pragma unroll
            for (int i = 0; i < TM; ++i) regM[i] = dup2(As[tRow * TM + i][k]);
            const U64* bp = reinterpret_cast<const U64*>(&Bs[k][tCol * TN]);
            U64 regN[TN / 2];
#pragma unroll
            for (int j = 0; j < TN / 2; ++j) regN[j] = bp[j];
#pragma unroll
            for (int i = 0; i < TM; ++i)
#pragma unroll
                for (int j = 0; j < TN / 2; ++j)
                    fma2(acc[i][j], regM[i], regN[j]);
        }
        __syncthreads();
    }

#pragma unroll
    for (int i = 0; i < TM; ++i) {
        int grow = rowBase + tRow * TM + i;
        if (grow >= N) continue;
#pragma unroll
        for (int j = 0; j < TN / 2; ++j) {
            int col = tCol * TN + 2 * j;
            float2 v = unpack2(acc[i][j]);
            v.x = fmaxf(v.x + bias[col], 0.f);
            v.y = fmaxf(v.y + bias[col + 1], 0.f);
            *reinterpret_cast<float2*>(&C[(long)grow * F + col]) = v;
        }
    }
}

// ---------------------------------------------------------------------------
// Layer-2 projection GEMM: p = h1 @ [W2_self | W2_nbr]   ([N,128]@[128,80])
// BM=64, BN=80, BK=16, TM=4, TN=10, 128 threads, f32x2 FMAs.
// B-tile load remaps columns: c<40 -> W2[k][c], else W2[128+k][c-40].
// ---------------------------------------------------------------------------
__global__ __launch_bounds__(128)
void gemm2_kernel(const float* __restrict__ A,   // h1 [N,128]
                  const float* __restrict__ W2,  // [256,40]
                  float* __restrict__ P, int N)  // [N,80]
{
    constexpr int BM = 64, BN = 80, BK = 16, TM = 4, TN = 10, NT = 128;

    __shared__ float As[BM][BK + 1];
    __shared__ float Bs[BK][BN];

    const int tid = threadIdx.x;
    const int rowBase = blockIdx.x * BM;
    const int tCol = tid & 7;         // 0..7   (BN/TN = 8)
    const int tRow = tid >> 3;        // 0..15  (BM/TM = 16)

    U64 acc[TM][TN / 2];
#pragma unroll
    for (int i = 0; i < TM; ++i)
#pragma unroll
        for (int j = 0; j < TN / 2; ++j) acc[i][j] = 0ull;

    for (int k0 = 0; k0 < F; k0 += BK) {
#pragma unroll
        for (int idx = tid; idx < BM * BK; idx += NT) {
            int row = idx / BK, col = idx % BK;
            int grow = rowBase + row;
            As[row][col] = (grow < N) ? A[(long)grow * F + k0 + col] : 0.f;
        }
#pragma unroll
        for (int idx = tid; idx < BK * BN; idx += NT) {
            int row = idx / BN, col = idx % BN;
            int kk = k0 + row;
            float v = (col < L2OUT) ? W2[(long)kk * L2OUT + col]
                                    : W2[(long)(F + kk) * L2OUT + (col - L2OUT)];
            Bs[row][col] = v;
        }
        __syncthreads();

#pragma unroll
        for (int k = 0; k < BK; ++k) {
            U64 regM[TM];
#pragma unroll
            for (int i = 0; i < TM; ++i) regM[i] = dup2(As[tRow * TM + i][k]);
            const U64* bp = reinterpret_cast<const U64*>(&Bs[k][tCol * TN]);
            U64 regN[TN / 2];
#pragma unroll
            for (int j = 0; j < TN / 2; ++j) regN[j] = bp[j];
#pragma unroll
            for (int i = 0; i < TM; ++i)
#pragma unroll
                for (int j = 0; j < TN / 2; ++j)
                    fma2(acc[i][j], regM[i], regN[j]);
        }
        __syncthreads();
    }

#pragma unroll
    for (int i = 0; i < TM; ++i) {
        int grow = rowBase + tRow * TM + i;
        if (grow >= N) continue;
#pragma unroll
        for (int j = 0; j < TN / 2; ++j) {
            int col = tCol * TN + 2 * j;
            float2 v = unpack2(acc[i][j]);
            *reinterpret_cast<float2*>(&P[(long)grow * 2 * L2OUT + col]) = v;
        }
    }
}

// ---------------------------------------------------------------------------
// Finalize: out[i][c] = p[batch[i]][c] + mean_j p[neigh[batch[i]][j]][40+c] + b2[c]
// Warp per output node; lane covers col=lane (and col=lane+32 for lanes 0..7).
// ---------------------------------------------------------------------------
__global__ __launch_bounds__(256)
void finalize40(const float* __restrict__ p,
                const int* __restrict__ neigh,
                const int* __restrict__ batch,
                const float* __restrict__ b2,
                float* __restrict__ out, int N)
{
    int w    = (blockIdx.x * blockDim.x + threadIdx.x) >> 5;
    int lane = threadIdx.x & 31;
    if (w >= N) return;
    int node  = batch[w];
    int myidx = neigh[node * DEG + lane];

    float acc1 = 0.f, acc2 = 0.f;
#pragma unroll
    for (int j = 0; j < DEG; ++j) {
        int nb = __shfl_sync(0xffffffffu, myidx, j);
        const float* base = p + (long)nb * 2 * L2OUT + L2OUT;
        acc1 += __ldg(base + lane);
        if (lane < L2OUT - 32) acc2 += __ldg(base + 32 + lane);
    }
    const float s = 1.0f / (float)DEG;
    const float* selfp = p + (long)node * 2 * L2OUT;
    out[(long)w * L2OUT + lane] = selfp[lane] + acc1 * s + b2[lane];
    if (lane < L2OUT - 32)
        out[(long)w * L2OUT + 32 + lane] = selfp[32 + lane] + acc2 * s + b2[32 + lane];
}

// ---------------------------------------------------------------------------
extern "C" void kernel_launch(void* const* d_in, const int* in_sizes, int n_in,
                              void* d_out, int out_size)
{
    const float* feats = (const float*)d_in[0];
    const int*   neigh = (const int*)  d_in[1];
    const int*   batch = (const int*)  d_in[2];
    const float* W1    = (const float*)d_in[3];
    const float* b1    = (const float*)d_in[4];
    const float* W2    = (const float*)d_in[5];
    const float* b2    = (const float*)d_in[6];
    float*       out   = (float*)d_out;

    const int N = in_sizes[0] / F;   // 50000
    const int B = in_sizes[2];       // = N

    float *m1, *h1, *pbuf;
    cudaGetSymbolAddress((void**)&m1,  g_m1);
    cudaGetSymbolAddress((void**)&h1,  g_h1);
    cudaGetSymbolAddress((void**)&pbuf, g_p);

    // Layer 1
    gather_mean128<<<(N * 32 + 255) / 256, 256>>>(feats, neigh, m1, N);
    gemm1_kernel<<<(N + 63) / 64, 256>>>(feats, m1, W1, b1, h1, N);

    // Layer 2 (project then gather)
    gemm2_kernel<<<(N + 63) / 64, 128>>>(h1, W2, pbuf, N);
    finalize40<<<(B * 32 + 255) / 256, 256>>>(pbuf, neigh, batch, b2, out, B);
}

// round 4
// speedup vs baseline: 1.9063x; 1.7167x over previous
#include <cuda_runtime.h>
#include <cuda_bf16.h>
#include <cstdint>

#define NMAX 50000
#define F 128
#define DEG 32
#define L2OUT 40

// Scratch (device globals — no allocation allowed).
__device__ float g_m1[NMAX * F];          // mean of neighbor feats
__device__ float g_h1[NMAX * F];          // layer-1 hidden
__device__ float g_p [NMAX * 2 * L2OUT];  // [p_self | p_nbr] projections

// ======================== helpers ======================
__device__ __forceinline__ uint32_t smem_u32(const void* p) {
    uint32_t a;
    asm("{ .reg .u64 t; cvta.to.shared.u64 t, %1; cvt.u32.u64 %0, t; }"
        : "=r"(a) : "l"(p));
    return a;
}
__device__ __forceinline__ void ldm_x4(uint32_t& r0, uint32_t& r1,
                                       uint32_t& r2, uint32_t& r3, uint32_t a) {
    asm volatile("ldmatrix.sync.aligned.m8n8.x4.shared.b16 {%0,%1,%2,%3}, [%4];"
                 : "=r"(r0), "=r"(r1), "=r"(r2), "=r"(r3) : "r"(a));
}
__device__ __forceinline__ void ldm_x2(uint32_t& r0, uint32_t& r1, uint32_t a) {
    asm volatile("ldmatrix.sync.aligned.m8n8.x2.shared.b16 {%0,%1}, [%2];"
                 : "=r"(r0), "=r"(r1) : "r"(a));
}
__device__ __forceinline__ void mma_bf16(float* c, const uint32_t* a,
                                         const uint32_t* b) {
    asm volatile(
        "mma.sync.aligned.m16n8k16.row.col.f32.bf16.bf16.f32 "
        "{%0,%1,%2,%3}, {%4,%5,%6,%7}, {%8,%9}, {%0,%1,%2,%3};"
        : "+f"(c[0]), "+f"(c[1]), "+f"(c[2]), "+f"(c[3])
        : "r"(a[0]), "r"(a[1]), "r"(a[2]), "r"(a[3]), "r"(b[0]), "r"(b[1]));
}
// Pack two floats into (bf16,bf16) hi parts; return residuals for lo pass.
__device__ __forceinline__ uint32_t bf16pair(float x, float y,
                                             float& rx, float& ry) {
    __nv_bfloat16 hx = __float2bfloat16(x);
    __nv_bfloat16 hy = __float2bfloat16(y);
    rx = x - __bfloat162float(hx);
    ry = y - __bfloat162float(hy);
    return ((uint32_t)__bfloat16_as_ushort(hy) << 16) |
           (uint32_t)__bfloat16_as_ushort(hx);
}
__device__ __forceinline__ uint32_t bf16pair_lo(float rx, float ry) {
    __nv_bfloat16 lx = __float2bfloat16(rx);
    __nv_bfloat16 ly = __float2bfloat16(ry);
    return ((uint32_t)__bfloat16_as_ushort(ly) << 16) |
           (uint32_t)__bfloat16_as_ushort(lx);
}

// ---------------------------------------------------------------------------
// Gather-mean width 128: dst[i] = mean_j src[neigh[i][j]]   (warp per node)
// ---------------------------------------------------------------------------
__global__ __launch_bounds__(256)
void gather_mean128(const float* __restrict__ src,
                    const int* __restrict__ neigh,
                    float* __restrict__ dst, int N)
{
    int w    = (blockIdx.x * blockDim.x + threadIdx.x) >> 5;
    int lane = threadIdx.x & 31;
    if (w >= N) return;
    int myidx = neigh[w * DEG + lane];

    float4 acc = make_float4(0.f, 0.f, 0.f, 0.f);
#pragma unroll
    for (int j = 0; j < DEG; ++j) {
        int nb = __shfl_sync(0xffffffffu, myidx, j);
        float4 v = __ldg(reinterpret_cast<const float4*>(src + (long)nb * F) + lane);
        acc.x += v.x; acc.y += v.y; acc.z += v.z; acc.w += v.w;
    }
    const float s = 1.0f / (float)DEG;
    acc.x *= s; acc.y *= s; acc.z *= s; acc.w *= s;
    reinterpret_cast<float4*>(dst + (long)w * F)[lane] = acc;
}

// ---------------------------------------------------------------------------
// GEMM1 via mma.sync bf16 hi/lo:  h1 = relu([feats | m1] @ W1 + b1)
// BM=128, BN=128, K=256 in 4 chunks of 64. 512 threads, 16 warps (4m x 4n),
// warp tile 32x32. SMEM tiles: [128][72] bf16 (row pad -> conflict-free).
// ---------------------------------------------------------------------------
#define LDT 72               // halfs per SMEM tile row (64 + 8 pad)
#define G1_AHI 0
#define G1_ALO 18432
#define G1_BHI 36864
#define G1_BLO 55296
#define G1_TOT 73728

__global__ __launch_bounds__(512, 1)
void gemm1_mma(const float* __restrict__ A1,   // feats [N,128]
               const float* __restrict__ A2,   // m1    [N,128]
               const float* __restrict__ W1,   // [256,128]
               const float* __restrict__ bias, // [128]
               float* __restrict__ C, int N)   // h1 [N,128]
{
    extern __shared__ __align__(16) char smem[];
    const uint32_t sbase = smem_u32(smem);
    const int tid   = threadIdx.x;
    const int wid   = tid >> 5;
    const int lane  = tid & 31;
    const int warpM = wid >> 2;          // 0..3
    const int warpN = wid & 3;           // 0..3
    const int rowBase = blockIdx.x * 128;

    // ldmatrix lane address components
    const uint32_t aRowSel = lane & 15;
    const uint32_t aKoff   = (uint32_t)(lane >> 4) << 3;
    const uint32_t bRowSel = lane & 7;
    const uint32_t bKoff   = (uint32_t)((lane >> 3) & 1) << 3;

    uint32_t aAddrHi[2], aAddrLo[2], bAddrHi[4], bAddrLo[4];
#pragma unroll
    for (int mt = 0; mt < 2; ++mt) {
        uint32_t off = ((warpM * 32 + mt * 16 + aRowSel) * LDT + aKoff) * 2;
        aAddrHi[mt] = sbase + G1_AHI + off;
        aAddrLo[mt] = sbase + G1_ALO + off;
    }
#pragma unroll
    for (int nt = 0; nt < 4; ++nt) {
        uint32_t off = ((warpN * 32 + nt * 8 + bRowSel) * LDT + bKoff) * 2;
        bAddrHi[nt] = sbase + G1_BHI + off;
        bAddrLo[nt] = sbase + G1_BLO + off;
    }

    float acc[2][4][4];
#pragma unroll
    for (int mt = 0; mt < 2; ++mt)
#pragma unroll
        for (int nt = 0; nt < 4; ++nt)
#pragma unroll
            for (int q = 0; q < 4; ++q) acc[mt][nt][q] = 0.f;

    for (int c = 0; c < 4; ++c) {
        const float* Asrc = (c < 2) ? A1 : A2;
        const int kOff = (c & 1) * 64;

        // A tile: 128 rows x 64 cols (float2 per thread-iter, coalesced)
#pragma unroll
        for (int i = tid; i < 4096; i += 512) {
            int row = i >> 5, cp = i & 31;
            int grow = rowBase + row;
            float2 v = make_float2(0.f, 0.f);
            if (grow < N)
                v = *reinterpret_cast<const float2*>(
                        &Asrc[(size_t)grow * F + kOff + cp * 2]);
            float rx, ry;
            uint32_t hi = bf16pair(v.x, v.y, rx, ry);
            uint32_t lo = bf16pair_lo(rx, ry);
            uint32_t o = (uint32_t)(row * LDT + cp * 2) * 2;
            *reinterpret_cast<uint32_t*>(smem + G1_AHI + o) = hi;
            *reinterpret_cast<uint32_t*>(smem + G1_ALO + o) = lo;
        }
        // B tile (transposed): Bs[n][k] = W1[c*64+k][n], n=0..127, k=0..63
#pragma unroll
        for (int i = tid; i < 4096; i += 512) {
            int n = i & 127, kp = i >> 7;         // kp 0..31
            int k = c * 64 + kp * 2;
            float bx = W1[(size_t)k * 128 + n];
            float by = W1[(size_t)(k + 1) * 128 + n];
            float rx, ry;
            uint32_t hi = bf16pair(bx, by, rx, ry);
            uint32_t lo = bf16pair_lo(rx, ry);
            uint32_t o = (uint32_t)(n * LDT + kp * 2) * 2;
            *reinterpret_cast<uint32_t*>(smem + G1_BHI + o) = hi;
            *reinterpret_cast<uint32_t*>(smem + G1_BLO + o) = lo;
        }
        __syncthreads();

#pragma unroll
        for (int ks = 0; ks < 4; ++ks) {
            const uint32_t k2 = ks * 32;   // 16 halves * 2 bytes
            uint32_t ahi[2][4], alo[2][4], bhi[4][2], blo[4][2];
#pragma unroll
            for (int mt = 0; mt < 2; ++mt) {
                ldm_x4(ahi[mt][0], ahi[mt][1], ahi[mt][2], ahi[mt][3],
                       aAddrHi[mt] + k2);
                ldm_x4(alo[mt][0], alo[mt][1], alo[mt][2], alo[mt][3],
                       aAddrLo[mt] + k2);
            }
#pragma unroll
            for (int nt = 0; nt < 4; ++nt) {
                ldm_x2(bhi[nt][0], bhi[nt][1], bAddrHi[nt] + k2);
                ldm_x2(blo[nt][0], blo[nt][1], bAddrLo[nt] + k2);
            }
#pragma unroll
            for (int mt = 0; mt < 2; ++mt)
#pragma unroll
                for (int nt = 0; nt < 4; ++nt) {
                    mma_bf16(acc[mt][nt], ahi[mt], bhi[nt]);
                    mma_bf16(acc[mt][nt], ahi[mt], blo[nt]);
                    mma_bf16(acc[mt][nt], alo[mt], bhi[nt]);
                }
        }
        __syncthreads();
    }

    // Epilogue: bias + relu, float2 stores
    const int g  = lane >> 2;
    const int qc = (lane & 3) * 2;
#pragma unroll
    for (int mt = 0; mt < 2; ++mt) {
#pragma unroll
        for (int nt = 0; nt < 4; ++nt) {
            int col = warpN * 32 + nt * 8 + qc;
            float bx = bias[col], by = bias[col + 1];
            int row0 = rowBase + warpM * 32 + mt * 16 + g;
            if (row0 < N) {
                float2 v = make_float2(fmaxf(acc[mt][nt][0] + bx, 0.f),
                                       fmaxf(acc[mt][nt][1] + by, 0.f));
                *reinterpret_cast<float2*>(&C[(size_t)row0 * F + col]) = v;
            }
            int row1 = row0 + 8;
            if (row1 < N) {
                float2 v = make_float2(fmaxf(acc[mt][nt][2] + bx, 0.f),
                                       fmaxf(acc[mt][nt][3] + by, 0.f));
                *reinterpret_cast<float2*>(&C[(size_t)row1 * F + col]) = v;
            }
        }
    }
}

// ---------------------------------------------------------------------------
// GEMM2 via mma.sync: p = h1 @ [W2_self | W2_nbr]   ([N,128]@[128,80])
// BM=128, BN=80, K=128 in 2 chunks of 64. 256 threads, 8 warps (4m x 2n),
// warp tile 32x40 (5 n-tiles).
// ---------------------------------------------------------------------------
#define G2_AHI 0
#define G2_ALO 18432
#define G2_BHI 36864
#define G2_BLO 48384
#define G2_TOT 59904

__global__ __launch_bounds__(256, 1)
void gemm2_mma(const float* __restrict__ A,   // h1 [N,128]
               const float* __restrict__ W2,  // [256,40]
               float* __restrict__ P, int N)  // [N,80]
{
    extern __shared__ __align__(16) char smem[];
    const uint32_t sbase = smem_u32(smem);
    const int tid   = threadIdx.x;
    const int wid   = tid >> 5;
    const int lane  = tid & 31;
    const int warpM = wid >> 1;          // 0..3
    const int warpN = wid & 1;           // 0..1
    const int rowBase = blockIdx.x * 128;

    const uint32_t aRowSel = lane & 15;
    const uint32_t aKoff   = (uint32_t)(lane >> 4) << 3;
    const uint32_t bRowSel = lane & 7;
    const uint32_t bKoff   = (uint32_t)((lane >> 3) & 1) << 3;

    uint32_t aAddrHi[2], aAddrLo[2], bAddrHi[5], bAddrLo[5];
#pragma unroll
    for (int mt = 0; mt < 2; ++mt) {
        uint32_t off = ((warpM * 32 + mt * 16 + aRowSel) * LDT + aKoff) * 2;
        aAddrHi[mt] = sbase + G2_AHI + off;
        aAddrLo[mt] = sbase + G2_ALO + off;
    }
#pragma unroll
    for (int nt = 0; nt < 5; ++nt) {
        uint32_t off = ((warpN * 40 + nt * 8 + bRowSel) * LDT + bKoff) * 2;
        bAddrHi[nt] = sbase + G2_BHI + off;
        bAddrLo[nt] = sbase + G2_BLO + off;
    }

    float acc[2][5][4];
#pragma unroll
    for (int mt = 0; mt < 2; ++mt)
#pragma unroll
        for (int nt = 0; nt < 5; ++nt)
#pragma unroll
            for (int q = 0; q < 4; ++q) acc[mt][nt][q] = 0.f;

    for (int c = 0; c < 2; ++c) {
        const int kOff = c * 64;
        // A tile 128x64
#pragma unroll
        for (int i = tid; i < 4096; i += 256) {
            int row = i >> 5, cp = i & 31;
            int grow = rowBase + row;
            float2 v = make_float2(0.f, 0.f);
            if (grow < N)
                v = *reinterpret_cast<const float2*>(
                        &A[(size_t)grow * F + kOff + cp * 2]);
            float rx, ry;
            uint32_t hi = bf16pair(v.x, v.y, rx, ry);
            uint32_t lo = bf16pair_lo(rx, ry);
            uint32_t o = (uint32_t)(row * LDT + cp * 2) * 2;
            *reinterpret_cast<uint32_t*>(smem + G2_AHI + o) = hi;
            *reinterpret_cast<uint32_t*>(smem + G2_ALO + o) = lo;
        }
        // B tile: Bs[n][k] = W2cat[kOff+k][n]; n 0..79, k 0..63
        for (int i = tid; i < 2560; i += 256) {
            int n = i % 80, kp = i / 80;          // kp 0..31
            int k = kOff + kp * 2;
            float bx, by;
            if (n < L2OUT) {
                bx = W2[(size_t)k * L2OUT + n];
                by = W2[(size_t)(k + 1) * L2OUT + n];
            } else {
                bx = W2[(size_t)(F + k) * L2OUT + (n - L2OUT)];
                by = W2[(size_t)(F + k + 1) * L2OUT + (n - L2OUT)];
            }
            float rx, ry;
            uint32_t hi = bf16pair(bx, by, rx, ry);
            uint32_t lo = bf16pair_lo(rx, ry);
            uint32_t o = (uint32_t)(n * LDT + kp * 2) * 2;
            *reinterpret_cast<uint32_t*>(smem + G2_BHI + o) = hi;
            *reinterpret_cast<uint32_t*>(smem + G2_BLO + o) = lo;
        }
        __syncthreads();

#pragma unroll
        for (int ks = 0; ks < 4; ++ks) {
            const uint32_t k2 = ks * 32;
            uint32_t ahi[2][4], alo[2][4], bhi[5][2], blo[5][2];
#pragma unroll
            for (int mt = 0; mt < 2; ++mt) {
                ldm_x4(ahi[mt][0], ahi[mt][1], ahi[mt][2], ahi[mt][3],
                       aAddrHi[mt] + k2);
                ldm_x4(alo[mt][0], alo[mt][1], alo[mt][2], alo[mt][3],
                       aAddrLo[mt] + k2);
            }
#pragma unroll
            for (int nt = 0; nt < 5; ++nt) {
                ldm_x2(bhi[nt][0], bhi[nt][1], bAddrHi[nt] + k2);
                ldm_x2(blo[nt][0], blo[nt][1], bAddrLo[nt] + k2);
            }
#pragma unroll
            for (int mt = 0; mt < 2; ++mt)
#pragma unroll
                for (int nt = 0; nt < 5; ++nt) {
                    mma_bf16(acc[mt][nt], ahi[mt], bhi[nt]);
                    mma_bf16(acc[mt][nt], ahi[mt], blo[nt]);
                    mma_bf16(acc[mt][nt], alo[mt], bhi[nt]);
                }
        }
        __syncthreads();
    }

    const int g  = lane >> 2;
    const int qc = (lane & 3) * 2;
#pragma unroll
    for (int mt = 0; mt < 2; ++mt) {
#pragma unroll
        for (int nt = 0; nt < 5; ++nt) {
            int col = warpN * 40 + nt * 8 + qc;
            int row0 = rowBase + warpM * 32 + mt * 16 + g;
            if (row0 < N) {
                float2 v = make_float2(acc[mt][nt][0], acc[mt][nt][1]);
                *reinterpret_cast<float2*>(&P[(size_t)row0 * 2 * L2OUT + col]) = v;
            }
            int row1 = row0 + 8;
            if (row1 < N) {
                float2 v = make_float2(acc[mt][nt][2], acc[mt][nt][3]);
                *reinterpret_cast<float2*>(&P[(size_t)row1 * 2 * L2OUT + col]) = v;
            }
        }
    }
}

// ---------------------------------------------------------------------------
// Finalize: out[i][c] = p[batch[i]][c] + mean_j p[neigh[batch[i]][j]][40+c] + b2[c]
// ---------------------------------------------------------------------------
__global__ __launch_bounds__(256)
void finalize40(const float* __restrict__ p,
                const int* __restrict__ neigh,
                const int* __restrict__ batch,
                const float* __restrict__ b2,
                float* __restrict__ out, int N)
{
    int w    = (blockIdx.x * blockDim.x + threadIdx.x) >> 5;
    int lane = threadIdx.x & 31;
    if (w >= N) return;
    int node  = batch[w];
    int myidx = neigh[node * DEG + lane];

    float acc1 = 0.f, acc2 = 0.f;
#pragma unroll
    for (int j = 0; j < DEG; ++j) {
        int nb = __shfl_sync(0xffffffffu, myidx, j);
        const float* base = p + (long)nb * 2 * L2OUT + L2OUT;
        acc1 += __ldg(base + lane);
        if (lane < L2OUT - 32) acc2 += __ldg(base + 32 + lane);
    }
    const float s = 1.0f / (float)DEG;
    const float* selfp = p + (long)node * 2 * L2OUT;
    out[(long)w * L2OUT + lane] = selfp[lane] + acc1 * s + b2[lane];
    if (lane < L2OUT - 32)
        out[(long)w * L2OUT + 32 + lane] = selfp[32 + lane] + acc2 * s + b2[32 + lane];
}

// ---------------------------------------------------------------------------
extern "C" void kernel_launch(void* const* d_in, const int* in_sizes, int n_in,
                              void* d_out, int out_size)
{
    const float* feats = (const float*)d_in[0];
    const int*   neigh = (const int*)  d_in[1];
    const int*   batch = (const int*)  d_in[2];
    const float* W1    = (const float*)d_in[3];
    const float* b1    = (const float*)d_in[4];
    const float* W2    = (const float*)d_in[5];
    const float* b2    = (const float*)d_in[6];
    float*       out   = (float*)d_out;

    const int N = in_sizes[0] / F;   // 50000
    const int B = in_sizes[2];       // = N

    float *m1, *h1, *pbuf;
    cudaGetSymbolAddress((void**)&m1,   g_m1);
    cudaGetSymbolAddress((void**)&h1,   g_h1);
    cudaGetSymbolAddress((void**)&pbuf, g_p);

    cudaFuncSetAttribute(gemm1_mma, cudaFuncAttributeMaxDynamicSharedMemorySize,
                         G1_TOT);
    cudaFuncSetAttribute(gemm2_mma, cudaFuncAttributeMaxDynamicSharedMemorySize,
                         G2_TOT);

    // Layer 1
    gather_mean128<<<(N * 32 + 255) / 256, 256>>>(feats, neigh, m1, N);
    gemm1_mma<<<(N + 127) / 128, 512, G1_TOT>>>(feats, m1, W1, b1, h1, N);

    // Layer 2 (project then gather)
    gemm2_mma<<<(N + 127) / 128, 256, G2_TOT>>>(h1, W2, pbuf, N);
    finalize40<<<(B * 32 + 255) / 256, 256>>>(pbuf, neigh, batch, b2, out, B);
}

// round 5
// speedup vs baseline: 2.0807x; 1.0915x over previous
#include <cuda_runtime.h>
#include <cuda_bf16.h>
#include <cstdint>

#define NMAX 50000
#define F 128
#define DEG 32
#define L2OUT 40

// Scratch (device globals — no allocation allowed).
__device__ __nv_bfloat16 g_fb16[NMAX * F];   // bf16 copy of feats
__device__ float g_m1[NMAX * F];             // mean of neighbor feats (fp32)
__device__ float g_p [NMAX * 2 * L2OUT];     // [p_self | p_nbr] projections

// ======================== helpers ======================
__device__ __forceinline__ uint32_t smem_u32(const void* p) {
    uint32_t a;
    asm("{ .reg .u64 t; cvta.to.shared.u64 t, %1; cvt.u32.u64 %0, t; }"
        : "=r"(a) : "l"(p));
    return a;
}
__device__ __forceinline__ void ldm_x4(uint32_t& r0, uint32_t& r1,
                                       uint32_t& r2, uint32_t& r3, uint32_t a) {
    asm volatile("ldmatrix.sync.aligned.m8n8.x4.shared.b16 {%0,%1,%2,%3}, [%4];"
                 : "=r"(r0), "=r"(r1), "=r"(r2), "=r"(r3) : "r"(a));
}
__device__ __forceinline__ void ldm_x2(uint32_t& r0, uint32_t& r1, uint32_t a) {
    asm volatile("ldmatrix.sync.aligned.m8n8.x2.shared.b16 {%0,%1}, [%2];"
                 : "=r"(r0), "=r"(r1) : "r"(a));
}
__device__ __forceinline__ void mma_bf16(float* c, const uint32_t* a,
                                         const uint32_t* b) {
    asm volatile(
        "mma.sync.aligned.m16n8k16.row.col.f32.bf16.bf16.f32 "
        "{%0,%1,%2,%3}, {%4,%5,%6,%7}, {%8,%9}, {%0,%1,%2,%3};"
        : "+f"(c[0]), "+f"(c[1]), "+f"(c[2]), "+f"(c[3])
        : "r"(a[0]), "r"(a[1]), "r"(a[2]), "r"(a[3]), "r"(b[0]), "r"(b[1]));
}
__device__ __forceinline__ uint32_t bf16pair(float x, float y,
                                             float& rx, float& ry) {
    __nv_bfloat16 hx = __float2bfloat16(x);
    __nv_bfloat16 hy = __float2bfloat16(y);
    rx = x - __bfloat162float(hx);
    ry = y - __bfloat162float(hy);
    return ((uint32_t)__bfloat16_as_ushort(hy) << 16) |
           (uint32_t)__bfloat16_as_ushort(hx);
}
__device__ __forceinline__ uint32_t bf16pair_lo(float rx, float ry) {
    __nv_bfloat16 lx = __float2bfloat16(rx);
    __nv_bfloat16 ly = __float2bfloat16(ry);
    return ((uint32_t)__bfloat16_as_ushort(ly) << 16) |
           (uint32_t)__bfloat16_as_ushort(lx);
}

// ---------------------------------------------------------------------------
// Convert feats fp32 -> bf16 (one pass).
// ---------------------------------------------------------------------------
__global__ __launch_bounds__(256)
void to_bf16(const float* __restrict__ src, __nv_bfloat16* __restrict__ dst,
             int n4)   // n4 = total / 4
{
    int i = blockIdx.x * 256 + threadIdx.x;
    if (i >= n4) return;
    float4 v = reinterpret_cast<const float4*>(src)[i];
    uint32_t p0 = ((uint32_t)__bfloat16_as_ushort(__float2bfloat16(v.y)) << 16) |
                  (uint32_t)__bfloat16_as_ushort(__float2bfloat16(v.x));
    uint32_t p1 = ((uint32_t)__bfloat16_as_ushort(__float2bfloat16(v.w)) << 16) |
                  (uint32_t)__bfloat16_as_ushort(__float2bfloat16(v.z));
    reinterpret_cast<uint2*>(dst)[i] = make_uint2(p0, p1);
}

// ---------------------------------------------------------------------------
// Gather-mean over bf16 feats (fp32 accumulation): warp per node.
// Lane reads 4 bf16 (8 B) per neighbor -> 256 B per row.
// ---------------------------------------------------------------------------
__global__ __launch_bounds__(256)
void gather_mean_bf16(const __nv_bfloat16* __restrict__ src,
                      const int* __restrict__ neigh,
                      float* __restrict__ dst, int N)
{
    int w    = (blockIdx.x * blockDim.x + threadIdx.x) >> 5;
    int lane = threadIdx.x & 31;
    if (w >= N) return;
    int myidx = neigh[w * DEG + lane];

    float4 acc = make_float4(0.f, 0.f, 0.f, 0.f);
#pragma unroll
    for (int j = 0; j < DEG; ++j) {
        int nb = __shfl_sync(0xffffffffu, myidx, j);
        uint2 u = __ldg(reinterpret_cast<const uint2*>(src + (size_t)nb * F) + lane);
        float2 a = __bfloat1622float2(*reinterpret_cast<__nv_bfloat162*>(&u.x));
        float2 b = __bfloat1622float2(*reinterpret_cast<__nv_bfloat162*>(&u.y));
        acc.x += a.x; acc.y += a.y; acc.z += b.x; acc.w += b.y;
    }
    const float s = 1.0f / (float)DEG;
    acc.x *= s; acc.y *= s; acc.z *= s; acc.w *= s;
    reinterpret_cast<float4*>(dst + (size_t)w * F)[lane] = acc;
}

// ---------------------------------------------------------------------------
// Fused GEMM: stage 1  h1 = relu([feats | m1] @ W1 + b1)   (in-SMEM only)
//             stage 2  p  = h1 @ [W2_self | W2_nbr]        (written to g_p)
// BM=128. Stage 1: BN=128, K=256 (4 chunks of 64), 16 warps (4m x 4n),
// warp tile 32x32, bf16 hi/lo (3 MMAs). Stage 2: BN=96 (80 real), K=128 in
// one SMEM-resident pass, warp tile 32x24.
// SMEM layout (dynamic):
//   region0 [0, 73728): stage-1 A/B tiles; reused for h1 hi/lo after stage 1
//   region1 [73728, 125952): W2cat hi/lo tiles (persistent)
// ---------------------------------------------------------------------------
#define LDT  72     // stage-1 tile: halves per row (64 + 8 pad)
#define LDT2 136    // stage-2 tile: halves per row (128 + 8 pad)
#define S1_AHI 0
#define S1_ALO 18432
#define S1_BHI 36864
#define S1_BLO 55296
#define H1_HI  0
#define H1_LO  34816
#define B2_HI  73728
#define B2_LO  99840
#define SM_TOT 125952

__global__ __launch_bounds__(512, 1)
void gemm_fused(const float* __restrict__ A1,   // feats [N,128]
                const float* __restrict__ A2,   // m1    [N,128]
                const float* __restrict__ W1,   // [256,128]
                const float* __restrict__ b1,   // [128]
                const float* __restrict__ W2,   // [256,40]
                float* __restrict__ P, int N)   // [N,80]
{
    extern __shared__ __align__(16) char smem[];
    const uint32_t sbase = smem_u32(smem);
    const int tid   = threadIdx.x;
    const int wid   = tid >> 5;
    const int lane  = tid & 31;
    const int warpM = wid >> 2;          // 0..3
    const int warpN = wid & 3;           // 0..3
    const int rowBase = blockIdx.x * 128;

    const uint32_t aRowSel = lane & 15;
    const uint32_t aKoff   = (uint32_t)(lane >> 4) << 3;
    const uint32_t bRowSel = lane & 7;
    const uint32_t bKoff   = (uint32_t)((lane >> 3) & 1) << 3;

    // ---- Load W2cat into stage-2 B tiles (independent of stage 1) ----
    // B2s[n][k] = W2cat[k][n], n=0..95 (n>=80 zero), k=0..127
    for (int i = tid; i < 6144; i += 512) {
        int n = i % 96, kp = i / 96;     // kp 0..63
        int k = kp * 2;
        float bx = 0.f, by = 0.f;
        if (n < L2OUT) {
            bx = W2[(size_t)k * L2OUT + n];
            by = W2[(size_t)(k + 1) * L2OUT + n];
        } else if (n < 2 * L2OUT) {
            bx = W2[(size_t)(F + k) * L2OUT + (n - L2OUT)];
            by = W2[(size_t)(F + k + 1) * L2OUT + (n - L2OUT)];
        }
        float rx, ry;
        uint32_t hi = bf16pair(bx, by, rx, ry);
        uint32_t lo = bf16pair_lo(rx, ry);
        uint32_t o = (uint32_t)(n * LDT2 + kp * 2) * 2;
        *reinterpret_cast<uint32_t*>(smem + B2_HI + o) = hi;
        *reinterpret_cast<uint32_t*>(smem + B2_LO + o) = lo;
    }

    // ======================= STAGE 1 =======================
    uint32_t aAddrHi[2], aAddrLo[2], bAddrHi[4], bAddrLo[4];
#pragma unroll
    for (int mt = 0; mt < 2; ++mt) {
        uint32_t off = ((warpM * 32 + mt * 16 + aRowSel) * LDT + aKoff) * 2;
        aAddrHi[mt] = sbase + S1_AHI + off;
        aAddrLo[mt] = sbase + S1_ALO + off;
    }
#pragma unroll
    for (int nt = 0; nt < 4; ++nt) {
        uint32_t off = ((warpN * 32 + nt * 8 + bRowSel) * LDT + bKoff) * 2;
        bAddrHi[nt] = sbase + S1_BHI + off;
        bAddrLo[nt] = sbase + S1_BLO + off;
    }

    float acc[2][4][4];
#pragma unroll
    for (int mt = 0; mt < 2; ++mt)
#pragma unroll
        for (int nt = 0; nt < 4; ++nt)
#pragma unroll
            for (int q = 0; q < 4; ++q) acc[mt][nt][q] = 0.f;

    for (int c = 0; c < 4; ++c) {
        const float* Asrc = (c < 2) ? A1 : A2;
        const int kOff = (c & 1) * 64;

#pragma unroll
        for (int i = tid; i < 4096; i += 512) {
            int row = i >> 5, cp = i & 31;
            int grow = rowBase + row;
            float2 v = make_float2(0.f, 0.f);
            if (grow < N)
                v = *reinterpret_cast<const float2*>(
                        &Asrc[(size_t)grow * F + kOff + cp * 2]);
            float rx, ry;
            uint32_t hi = bf16pair(v.x, v.y, rx, ry);
            uint32_t lo = bf16pair_lo(rx, ry);
            uint32_t o = (uint32_t)(row * LDT + cp * 2) * 2;
            *reinterpret_cast<uint32_t*>(smem + S1_AHI + o) = hi;
            *reinterpret_cast<uint32_t*>(smem + S1_ALO + o) = lo;
        }
#pragma unroll
        for (int i = tid; i < 4096; i += 512) {
            int n = i & 127, kp = i >> 7;
            int k = c * 64 + kp * 2;
            float bx = W1[(size_t)k * 128 + n];
            float by = W1[(size_t)(k + 1) * 128 + n];
            float rx, ry;
            uint32_t hi = bf16pair(bx, by, rx, ry);
            uint32_t lo = bf16pair_lo(rx, ry);
            uint32_t o = (uint32_t)(n * LDT + kp * 2) * 2;
            *reinterpret_cast<uint32_t*>(smem + S1_BHI + o) = hi;
            *reinterpret_cast<uint32_t*>(smem + S1_BLO + o) = lo;
        }
        __syncthreads();

#pragma unroll
        for (int ks = 0; ks < 4; ++ks) {
            const uint32_t k2 = ks * 32;
            uint32_t ahi[2][4], alo[2][4], bhi[4][2], blo[4][2];
#pragma unroll
            for (int mt = 0; mt < 2; ++mt) {
                ldm_x4(ahi[mt][0], ahi[mt][1], ahi[mt][2], ahi[mt][3],
                       aAddrHi[mt] + k2);
                ldm_x4(alo[mt][0], alo[mt][1], alo[mt][2], alo[mt][3],
                       aAddrLo[mt] + k2);
            }
#pragma unroll
            for (int nt = 0; nt < 4; ++nt) {
                ldm_x2(bhi[nt][0], bhi[nt][1], bAddrHi[nt] + k2);
                ldm_x2(blo[nt][0], blo[nt][1], bAddrLo[nt] + k2);
            }
#pragma unroll
            for (int mt = 0; mt < 2; ++mt)
#pragma unroll
                for (int nt = 0; nt < 4; ++nt) {
                    mma_bf16(acc[mt][nt], ahi[mt], bhi[nt]);
                    mma_bf16(acc[mt][nt], ahi[mt], blo[nt]);
                    mma_bf16(acc[mt][nt], alo[mt], bhi[nt]);
                }
        }
        __syncthreads();
    }

    // ---- bias + relu; convert h1 tile to bf16 hi/lo in SMEM (reuse region0)
    {
        const int g  = lane >> 2;
        const int qc = (lane & 3) * 2;
#pragma unroll
        for (int mt = 0; mt < 2; ++mt) {
#pragma unroll
            for (int nt = 0; nt < 4; ++nt) {
                int col = warpN * 32 + nt * 8 + qc;
                float bx = b1[col], by = b1[col + 1];
                int rl0 = warpM * 32 + mt * 16 + g;
                int rl1 = rl0 + 8;
                float v0 = fmaxf(acc[mt][nt][0] + bx, 0.f);
                float v1 = fmaxf(acc[mt][nt][1] + by, 0.f);
                float v2 = fmaxf(acc[mt][nt][2] + bx, 0.f);
                float v3 = fmaxf(acc[mt][nt][3] + by, 0.f);
                float rx, ry;
                uint32_t hi0 = bf16pair(v0, v1, rx, ry);
                uint32_t lo0 = bf16pair_lo(rx, ry);
                uint32_t o0 = (uint32_t)(rl0 * LDT2 + col) * 2;
                uint32_t hi1 = bf16pair(v2, v3, rx, ry);
                uint32_t lo1 = bf16pair_lo(rx, ry);
                uint32_t o1 = (uint32_t)(rl1 * LDT2 + col) * 2;
                *reinterpret_cast<uint32_t*>(smem + H1_HI + o0) = hi0;
                *reinterpret_cast<uint32_t*>(smem + H1_LO + o0) = lo0;
                *reinterpret_cast<uint32_t*>(smem + H1_HI + o1) = hi1;
                *reinterpret_cast<uint32_t*>(smem + H1_LO + o1) = lo1;
            }
        }
    }
    __syncthreads();

    // ======================= STAGE 2 =======================
    // p[128 x 96(80)] = h1[128 x 128] @ W2cat^T ; warp tile 32 x 24
    uint32_t a2Hi[2], a2Lo[2], b2Hi[3], b2Lo[3];
#pragma unroll
    for (int mt = 0; mt < 2; ++mt) {
        uint32_t off = ((warpM * 32 + mt * 16 + aRowSel) * LDT2 + aKoff) * 2;
        a2Hi[mt] = sbase + H1_HI + off;
        a2Lo[mt] = sbase + H1_LO + off;
    }
#pragma unroll
    for (int nt = 0; nt < 3; ++nt) {
        uint32_t off = ((warpN * 24 + nt * 8 + bRowSel) * LDT2 + bKoff) * 2;
        b2Hi[nt] = sbase + B2_HI + off;
        b2Lo[nt] = sbase + B2_LO + off;
    }

    float acc2[2][3][4];
#pragma unroll
    for (int mt = 0; mt < 2; ++mt)
#pragma unroll
        for (int nt = 0; nt < 3; ++nt)
#pragma unroll
            for (int q = 0; q < 4; ++q) acc2[mt][nt][q] = 0.f;

#pragma unroll
    for (int ks = 0; ks < 8; ++ks) {
        const uint32_t k2 = ks * 32;
        uint32_t ahi[2][4], alo[2][4], bhi[3][2], blo[3][2];
#pragma unroll
        for (int mt = 0; mt < 2; ++mt) {
            ldm_x4(ahi[mt][0], ahi[mt][1], ahi[mt][2], ahi[mt][3], a2Hi[mt] + k2);
            ldm_x4(alo[mt][0], alo[mt][1], alo[mt][2], alo[mt][3], a2Lo[mt] + k2);
        }
#pragma unroll
        for (int nt = 0; nt < 3; ++nt) {
            ldm_x2(bhi[nt][0], bhi[nt][1], b2Hi[nt] + k2);
            ldm_x2(blo[nt][0], blo[nt][1], b2Lo[nt] + k2);
        }
#pragma unroll
        for (int mt = 0; mt < 2; ++mt)
#pragma unroll
            for (int nt = 0; nt < 3; ++nt) {
                mma_bf16(acc2[mt][nt], ahi[mt], bhi[nt]);
                mma_bf16(acc2[mt][nt], ahi[mt], blo[nt]);
                mma_bf16(acc2[mt][nt], alo[mt], bhi[nt]);
            }
    }

    // Store p
    {
        const int g  = lane >> 2;
        const int qc = (lane & 3) * 2;
#pragma unroll
        for (int mt = 0; mt < 2; ++mt) {
#pragma unroll
            for (int nt = 0; nt < 3; ++nt) {
                int col = warpN * 24 + nt * 8 + qc;
                if (col >= 2 * L2OUT) continue;
                int row0 = rowBase + warpM * 32 + mt * 16 + g;
                if (row0 < N) {
                    float2 v = make_float2(acc2[mt][nt][0], acc2[mt][nt][1]);
                    *reinterpret_cast<float2*>(&P[(size_t)row0 * 2 * L2OUT + col]) = v;
                }
                int row1 = row0 + 8;
                if (row1 < N) {
                    float2 v = make_float2(acc2[mt][nt][2], acc2[mt][nt][3]);
                    *reinterpret_cast<float2*>(&P[(size_t)row1 * 2 * L2OUT + col]) = v;
                }
            }
        }
    }
}

// ---------------------------------------------------------------------------
// Finalize: out[i][c] = p[batch[i]][c] + mean_j p[neigh[batch[i]][j]][40+c] + b2[c]
// ---------------------------------------------------------------------------
__global__ __launch_bounds__(256)
void finalize40(const float* __restrict__ p,
                const int* __restrict__ neigh,
                const int* __restrict__ batch,
                const float* __restrict__ b2,
                float* __restrict__ out, int N)
{
    int w    = (blockIdx.x * blockDim.x + threadIdx.x) >> 5;
    int lane = threadIdx.x & 31;
    if (w >= N) return;
    int node  = batch[w];
    int myidx = neigh[node * DEG + lane];

    float acc1 = 0.f, acc2 = 0.f;
#pragma unroll
    for (int j = 0; j < DEG; ++j) {
        int nb = __shfl_sync(0xffffffffu, myidx, j);
        const float* base = p + (size_t)nb * 2 * L2OUT + L2OUT;
        acc1 += __ldg(base + lane);
        if (lane < L2OUT - 32) acc2 += __ldg(base + 32 + lane);
    }
    const float s = 1.0f / (float)DEG;
    const float* selfp = p + (size_t)node * 2 * L2OUT;
    out[(size_t)w * L2OUT + lane] = selfp[lane] + acc1 * s + b2[lane];
    if (lane < L2OUT - 32)
        out[(size_t)w * L2OUT + 32 + lane] = selfp[32 + lane] + acc2 * s + b2[32 + lane];
}

// ---------------------------------------------------------------------------
extern "C" void kernel_launch(void* const* d_in, const int* in_sizes, int n_in,
                              void* d_out, int out_size)
{
    const float* feats = (const float*)d_in[0];
    const int*   neigh = (const int*)  d_in[1];
    const int*   batch = (const int*)  d_in[2];
    const float* W1    = (const float*)d_in[3];
    const float* b1    = (const float*)d_in[4];
    const float* W2    = (const float*)d_in[5];
    const float* b2    = (const float*)d_in[6];
    float*       out   = (float*)d_out;

    const int N = in_sizes[0] / F;   // 50000
    const int B = in_sizes[2];       // = N

    float *m1, *pbuf;
    __nv_bfloat16* fb16;
    cudaGetSymbolAddress((void**)&m1,   g_m1);
    cudaGetSymbolAddress((void**)&pbuf, g_p);
    cudaGetSymbolAddress((void**)&fb16, g_fb16);

    cudaFuncSetAttribute(gemm_fused, cudaFuncAttributeMaxDynamicSharedMemorySize,
                         SM_TOT);

    const int n4 = N * F / 4;
    to_bf16<<<(n4 + 255) / 256, 256>>>(feats, fb16, n4);
    gather_mean_bf16<<<(N * 32 + 255) / 256, 256>>>(fb16, neigh, m1, N);
    gemm_fused<<<(N + 127) / 128, 512, SM_TOT>>>(feats, m1, W1, b1, W2, pbuf, N);
    finalize40<<<(B * 32 + 255) / 256, 256>>>(pbuf, neigh, batch, b2, out, B);
}

// round 6
// speedup vs baseline: 2.4728x; 1.1884x over previous
#include <cuda_runtime.h>
#include <cuda_bf16.h>
#include <cstdint>

#define NMAX 50000
#define F 128
#define DEG 32
#define L2OUT 40

typedef __nv_bfloat16 bf16;

// Scratch (device globals — no allocation allowed).
__device__ bf16 g_fhi[NMAX * F];          // feats hi
__device__ bf16 g_flo[NMAX * F];          // feats lo (residual)
__device__ bf16 g_m1hi[NMAX * F];         // neighbor-mean hi
__device__ bf16 g_m1lo[NMAX * F];         // neighbor-mean lo
__device__ bf16 g_w1hi[128 * 256];        // W1^T hi  [n][k]
__device__ bf16 g_w1lo[128 * 256];        // W1^T lo
__device__ bf16 g_w2hi[96 * 128];         // W2cat^T hi [n][k] (n>=80 zero)
__device__ bf16 g_w2lo[96 * 128];         // W2cat^T lo
__device__ float g_ps[NMAX * L2OUT];      // self projection (fp32)
__device__ bf16  g_pn[NMAX * L2OUT];      // neighbor projection (bf16)

// ======================== helpers ======================
__device__ __forceinline__ uint32_t smem_u32(const void* p) {
    uint32_t a;
    asm("{ .reg .u64 t; cvta.to.shared.u64 t, %1; cvt.u32.u64 %0, t; }"
        : "=r"(a) : "l"(p));
    return a;
}
__device__ __forceinline__ void ldm_x4(uint32_t& r0, uint32_t& r1,
                                       uint32_t& r2, uint32_t& r3, uint32_t a) {
    asm volatile("ldmatrix.sync.aligned.m8n8.x4.shared.b16 {%0,%1,%2,%3}, [%4];"
                 : "=r"(r0), "=r"(r1), "=r"(r2), "=r"(r3) : "r"(a));
}
__device__ __forceinline__ void ldm_x2(uint32_t& r0, uint32_t& r1, uint32_t a) {
    asm volatile("ldmatrix.sync.aligned.m8n8.x2.shared.b16 {%0,%1}, [%2];"
                 : "=r"(r0), "=r"(r1) : "r"(a));
}
__device__ __forceinline__ void mma_bf16(float* c, const uint32_t* a,
                                         const uint32_t* b) {
    asm volatile(
        "mma.sync.aligned.m16n8k16.row.col.f32.bf16.bf16.f32 "
        "{%0,%1,%2,%3}, {%4,%5,%6,%7}, {%8,%9}, {%0,%1,%2,%3};"
        : "+f"(c[0]), "+f"(c[1]), "+f"(c[2]), "+f"(c[3])
        : "r"(a[0]), "r"(a[1]), "r"(a[2]), "r"(a[3]), "r"(b[0]), "r"(b[1]));
}
__device__ __forceinline__ uint32_t bf16pair(float x, float y,
                                             float& rx, float& ry) {
    bf16 hx = __float2bfloat16(x);
    bf16 hy = __float2bfloat16(y);
    rx = x - __bfloat162float(hx);
    ry = y - __bfloat162float(hy);
    return ((uint32_t)__bfloat16_as_ushort(hy) << 16) |
           (uint32_t)__bfloat16_as_ushort(hx);
}
__device__ __forceinline__ uint32_t bf16pair_lo(float rx, float ry) {
    bf16 lx = __float2bfloat16(rx);
    bf16 ly = __float2bfloat16(ry);
    return ((uint32_t)__bfloat16_as_ushort(ly) << 16) |
           (uint32_t)__bfloat16_as_ushort(lx);
}
__device__ __forceinline__ uint32_t pack_bf16(float x, float y) {
    return ((uint32_t)__bfloat16_as_ushort(__float2bfloat16(y)) << 16) |
           (uint32_t)__bfloat16_as_ushort(__float2bfloat16(x));
}

// ---------------------------------------------------------------------------
// One-time weight prep: W1^T hi/lo and W2cat^T hi/lo.
// ---------------------------------------------------------------------------
__global__ __launch_bounds__(256)
void wprep(const float* __restrict__ W1, const float* __restrict__ W2,
           bf16* __restrict__ w1hi, bf16* __restrict__ w1lo,
           bf16* __restrict__ w2hi, bf16* __restrict__ w2lo)
{
    int i = blockIdx.x * 256 + threadIdx.x;
    if (i < 128 * 256) {                         // W1^T: n=i>>8, k=i&255
        int n = i >> 8, k = i & 255;
        float v = W1[(size_t)k * 128 + n];
        bf16 h = __float2bfloat16(v);
        w1hi[i] = h;
        w1lo[i] = __float2bfloat16(v - __bfloat162float(h));
    } else if (i < 128 * 256 + 96 * 128) {       // W2cat^T
        int j = i - 128 * 256;
        int n = j >> 7, k = j & 127;
        float v = 0.f;
        if (n < L2OUT)          v = W2[(size_t)k * L2OUT + n];
        else if (n < 2 * L2OUT) v = W2[(size_t)(F + k) * L2OUT + (n - L2OUT)];
        bf16 h = __float2bfloat16(v);
        w2hi[j] = h;
        w2lo[j] = __float2bfloat16(v - __bfloat162float(h));
    }
}

// ---------------------------------------------------------------------------
// feats fp32 -> hi/lo bf16 (one pass).
// ---------------------------------------------------------------------------
__global__ __launch_bounds__(256)
void featprep(const float* __restrict__ src, bf16* __restrict__ hi,
              bf16* __restrict__ lo, int n4)
{
    int i = blockIdx.x * 256 + threadIdx.x;
    if (i >= n4) return;
    float4 v = reinterpret_cast<const float4*>(src)[i];
    float r0, r1, r2, r3;
    uint32_t h0 = bf16pair(v.x, v.y, r0, r1);
    uint32_t h1 = bf16pair(v.z, v.w, r2, r3);
    uint32_t l0 = bf16pair_lo(r0, r1);
    uint32_t l1 = bf16pair_lo(r2, r3);
    reinterpret_cast<uint2*>(hi)[i] = make_uint2(h0, h1);
    reinterpret_cast<uint2*>(lo)[i] = make_uint2(l0, l1);
}

// ---------------------------------------------------------------------------
// Gather-mean over bf16 feats (fp32 accumulation), emit hi/lo bf16.
// ---------------------------------------------------------------------------
__global__ __launch_bounds__(256)
void gather_mean_bf16(const bf16* __restrict__ src,
                      const int* __restrict__ neigh,
                      bf16* __restrict__ dhi, bf16* __restrict__ dlo, int N)
{
    int w    = (blockIdx.x * blockDim.x + threadIdx.x) >> 5;
    int lane = threadIdx.x & 31;
    if (w >= N) return;
    int myidx = neigh[w * DEG + lane];

    float4 acc = make_float4(0.f, 0.f, 0.f, 0.f);
#pragma unroll
    for (int j = 0; j < DEG; ++j) {
        int nb = __shfl_sync(0xffffffffu, myidx, j);
        uint2 u = __ldg(reinterpret_cast<const uint2*>(src + (size_t)nb * F) + lane);
        float2 a = __bfloat1622float2(*reinterpret_cast<__nv_bfloat162*>(&u.x));
        float2 b = __bfloat1622float2(*reinterpret_cast<__nv_bfloat162*>(&u.y));
        acc.x += a.x; acc.y += a.y; acc.z += b.x; acc.w += b.y;
    }
    const float s = 1.0f / (float)DEG;
    acc.x *= s; acc.y *= s; acc.z *= s; acc.w *= s;
    float r0, r1, r2, r3;
    uint32_t h0 = bf16pair(acc.x, acc.y, r0, r1);
    uint32_t h1 = bf16pair(acc.z, acc.w, r2, r3);
    uint32_t l0 = bf16pair_lo(r0, r1);
    uint32_t l1 = bf16pair_lo(r2, r3);
    reinterpret_cast<uint2*>(dhi + (size_t)w * F)[lane] = make_uint2(h0, h1);
    reinterpret_cast<uint2*>(dlo + (size_t)w * F)[lane] = make_uint2(l0, l1);
}

// ---------------------------------------------------------------------------
// Fused GEMM (tiles are pure copies now):
//   stage 1: h1 = relu([feats | m1] @ W1 + b1)  (SMEM only)
//   stage 2: ps = h1 @ W2_self (fp32), pn = h1 @ W2_nbr (bf16)
// ---------------------------------------------------------------------------
#define LDT  72
#define LDT2 136
#define S1_AHI 0
#define S1_ALO 18432
#define S1_BHI 36864
#define S1_BLO 55296
#define H1_HI  0
#define H1_LO  34816
#define B2_HI  73728
#define B2_LO  99840
#define SM_TOT 125952

__global__ __launch_bounds__(512, 1)
void gemm_fused(const bf16* __restrict__ fhi, const bf16* __restrict__ flo,
                const bf16* __restrict__ m1hi, const bf16* __restrict__ m1lo,
                const bf16* __restrict__ w1hi, const bf16* __restrict__ w1lo,
                const bf16* __restrict__ w2hi, const bf16* __restrict__ w2lo,
                const float* __restrict__ b1,
                float* __restrict__ PS, bf16* __restrict__ PN, int N)
{
    extern __shared__ __align__(16) char smem[];
    const uint32_t sbase = smem_u32(smem);
    const int tid   = threadIdx.x;
    const int wid   = tid >> 5;
    const int lane  = tid & 31;
    const int warpM = wid >> 2;
    const int warpN = wid & 3;
    const int rowBase = blockIdx.x * 128;

    const uint32_t aRowSel = lane & 15;
    const uint32_t aKoff   = (uint32_t)(lane >> 4) << 3;
    const uint32_t bRowSel = lane & 7;
    const uint32_t bKoff   = (uint32_t)((lane >> 3) & 1) << 3;

    // ---- W2cat tiles (persistent, plain copies) ----
#pragma unroll
    for (int i = tid; i < 1536; i += 512) {
        int n = i >> 4, h8 = i & 15;
        uint4 vh = *reinterpret_cast<const uint4*>(w2hi + n * 128 + h8 * 8);
        uint4 vl = *reinterpret_cast<const uint4*>(w2lo + n * 128 + h8 * 8);
        uint32_t o = (uint32_t)(n * LDT2 + h8 * 8) * 2;
        *reinterpret_cast<uint4*>(smem + B2_HI + o) = vh;
        *reinterpret_cast<uint4*>(smem + B2_LO + o) = vl;
    }

    // ======================= STAGE 1 =======================
    uint32_t aAddrHi[2], aAddrLo[2], bAddrHi[4], bAddrLo[4];
#pragma unroll
    for (int mt = 0; mt < 2; ++mt) {
        uint32_t off = ((warpM * 32 + mt * 16 + aRowSel) * LDT + aKoff) * 2;
        aAddrHi[mt] = sbase + S1_AHI + off;
        aAddrLo[mt] = sbase + S1_ALO + off;
    }
#pragma unroll
    for (int nt = 0; nt < 4; ++nt) {
        uint32_t off = ((warpN * 32 + nt * 8 + bRowSel) * LDT + bKoff) * 2;
        bAddrHi[nt] = sbase + S1_BHI + off;
        bAddrLo[nt] = sbase + S1_BLO + off;
    }

    float acc[2][4][4];
#pragma unroll
    for (int mt = 0; mt < 2; ++mt)
#pragma unroll
        for (int nt = 0; nt < 4; ++nt)
#pragma unroll
            for (int q = 0; q < 4; ++q) acc[mt][nt][q] = 0.f;

    for (int c = 0; c < 4; ++c) {
        const bf16* srcHi = (c < 2) ? fhi : m1hi;
        const bf16* srcLo = (c < 2) ? flo : m1lo;
        const int kOff = (c & 1) * 64;

        // A tile: 128 rows x 64 halves, uint4 copies
#pragma unroll
        for (int i = tid; i < 1024; i += 512) {
            int row = i >> 3, h8 = i & 7;
            int grow = rowBase + row;
            uint4 vh = make_uint4(0, 0, 0, 0), vl = make_uint4(0, 0, 0, 0);
            if (grow < N) {
                vh = *reinterpret_cast<const uint4*>(
                        srcHi + (size_t)grow * F + kOff + h8 * 8);
                vl = *reinterpret_cast<const uint4*>(
                        srcLo + (size_t)grow * F + kOff + h8 * 8);
            }
            uint32_t o = (uint32_t)(row * LDT + h8 * 8) * 2;
            *reinterpret_cast<uint4*>(smem + S1_AHI + o) = vh;
            *reinterpret_cast<uint4*>(smem + S1_ALO + o) = vl;
        }
        // B tile: W1^T rows, k slice c*64..+63
#pragma unroll
        for (int i = tid; i < 1024; i += 512) {
            int n = i >> 3, h8 = i & 7;
            uint4 vh = *reinterpret_cast<const uint4*>(
                          w1hi + n * 256 + c * 64 + h8 * 8);
            uint4 vl = *reinterpret_cast<const uint4*>(
                          w1lo + n * 256 + c * 64 + h8 * 8);
            uint32_t o = (uint32_t)(n * LDT + h8 * 8) * 2;
            *reinterpret_cast<uint4*>(smem + S1_BHI + o) = vh;
            *reinterpret_cast<uint4*>(smem + S1_BLO + o) = vl;
        }
        __syncthreads();

#pragma unroll
        for (int ks = 0; ks < 4; ++ks) {
            const uint32_t k2 = ks * 32;
            uint32_t ahi[2][4], alo[2][4], bhi[4][2], blo[4][2];
#pragma unroll
            for (int mt = 0; mt < 2; ++mt) {
                ldm_x4(ahi[mt][0], ahi[mt][1], ahi[mt][2], ahi[mt][3],
                       aAddrHi[mt] + k2);
                ldm_x4(alo[mt][0], alo[mt][1], alo[mt][2], alo[mt][3],
                       aAddrLo[mt] + k2);
            }
#pragma unroll
            for (int nt = 0; nt < 4; ++nt) {
                ldm_x2(bhi[nt][0], bhi[nt][1], bAddrHi[nt] + k2);
                ldm_x2(blo[nt][0], blo[nt][1], bAddrLo[nt] + k2);
            }
#pragma unroll
            for (int mt = 0; mt < 2; ++mt)
#pragma unroll
                for (int nt = 0; nt < 4; ++nt) {
                    mma_bf16(acc[mt][nt], ahi[mt], bhi[nt]);
                    mma_bf16(acc[mt][nt], ahi[mt], blo[nt]);
                    mma_bf16(acc[mt][nt], alo[mt], bhi[nt]);
                }
        }
        __syncthreads();
    }

    // bias + relu -> h1 hi/lo in SMEM
    {
        const int g  = lane >> 2;
        const int qc = (lane & 3) * 2;
#pragma unroll
        for (int mt = 0; mt < 2; ++mt) {
#pragma unroll
            for (int nt = 0; nt < 4; ++nt) {
                int col = warpN * 32 + nt * 8 + qc;
                float bx = b1[col], by = b1[col + 1];
                int rl0 = warpM * 32 + mt * 16 + g;
                int rl1 = rl0 + 8;
                float v0 = fmaxf(acc[mt][nt][0] + bx, 0.f);
                float v1 = fmaxf(acc[mt][nt][1] + by, 0.f);
                float v2 = fmaxf(acc[mt][nt][2] + bx, 0.f);
                float v3 = fmaxf(acc[mt][nt][3] + by, 0.f);
                float rx, ry;
                uint32_t hi0 = bf16pair(v0, v1, rx, ry);
                uint32_t lo0 = bf16pair_lo(rx, ry);
                uint32_t o0 = (uint32_t)(rl0 * LDT2 + col) * 2;
                uint32_t hi1 = bf16pair(v2, v3, rx, ry);
                uint32_t lo1 = bf16pair_lo(rx, ry);
                uint32_t o1 = (uint32_t)(rl1 * LDT2 + col) * 2;
                *reinterpret_cast<uint32_t*>(smem + H1_HI + o0) = hi0;
                *reinterpret_cast<uint32_t*>(smem + H1_LO + o0) = lo0;
                *reinterpret_cast<uint32_t*>(smem + H1_HI + o1) = hi1;
                *reinterpret_cast<uint32_t*>(smem + H1_LO + o1) = lo1;
            }
        }
    }
    __syncthreads();

    // ======================= STAGE 2 =======================
    uint32_t a2Hi[2], a2Lo[2], b2Hi[3], b2Lo[3];
#pragma unroll
    for (int mt = 0; mt < 2; ++mt) {
        uint32_t off = ((warpM * 32 + mt * 16 + aRowSel) * LDT2 + aKoff) * 2;
        a2Hi[mt] = sbase + H1_HI + off;
        a2Lo[mt] = sbase + H1_LO + off;
    }
#pragma unroll
    for (int nt = 0; nt < 3; ++nt) {
        uint32_t off = ((warpN * 24 + nt * 8 + bRowSel) * LDT2 + bKoff) * 2;
        b2Hi[nt] = sbase + B2_HI + off;
        b2Lo[nt] = sbase + B2_LO + off;
    }

    float acc2[2][3][4];
#pragma unroll
    for (int mt = 0; mt < 2; ++mt)
#pragma unroll
        for (int nt = 0; nt < 3; ++nt)
#pragma unroll
            for (int q = 0; q < 4; ++q) acc2[mt][nt][q] = 0.f;

#pragma unroll
    for (int ks = 0; ks < 8; ++ks) {
        const uint32_t k2 = ks * 32;
        uint32_t ahi[2][4], alo[2][4], bhi[3][2], blo[3][2];
#pragma unroll
        for (int mt = 0; mt < 2; ++mt) {
            ldm_x4(ahi[mt][0], ahi[mt][1], ahi[mt][2], ahi[mt][3], a2Hi[mt] + k2);
            ldm_x4(alo[mt][0], alo[mt][1], alo[mt][2], alo[mt][3], a2Lo[mt] + k2);
        }
#pragma unroll
        for (int nt = 0; nt < 3; ++nt) {
            ldm_x2(bhi[nt][0], bhi[nt][1], b2Hi[nt] + k2);
            ldm_x2(blo[nt][0], blo[nt][1], b2Lo[nt] + k2);
        }
#pragma unroll
        for (int mt = 0; mt < 2; ++mt)
#pragma unroll
            for (int nt = 0; nt < 3; ++nt) {
                mma_bf16(acc2[mt][nt], ahi[mt], bhi[nt]);
                mma_bf16(acc2[mt][nt], ahi[mt], blo[nt]);
                mma_bf16(acc2[mt][nt], alo[mt], bhi[nt]);
            }
    }

    // Store: cols 0..39 -> PS (fp32), 40..79 -> PN (bf16), 80..95 dropped
    {
        const int g  = lane >> 2;
        const int qc = (lane & 3) * 2;
#pragma unroll
        for (int mt = 0; mt < 2; ++mt) {
#pragma unroll
            for (int nt = 0; nt < 3; ++nt) {
                int col = warpN * 24 + nt * 8 + qc;
                if (col >= 2 * L2OUT) continue;
                int row0 = rowBase + warpM * 32 + mt * 16 + g;
                int row1 = row0 + 8;
                if (col < L2OUT) {
                    if (row0 < N)
                        *reinterpret_cast<float2*>(&PS[(size_t)row0 * L2OUT + col]) =
                            make_float2(acc2[mt][nt][0], acc2[mt][nt][1]);
                    if (row1 < N)
                        *reinterpret_cast<float2*>(&PS[(size_t)row1 * L2OUT + col]) =
                            make_float2(acc2[mt][nt][2], acc2[mt][nt][3]);
                } else {
                    int cn = col - L2OUT;
                    if (row0 < N)
                        *reinterpret_cast<uint32_t*>(PN + (size_t)row0 * L2OUT + cn) =
                            pack_bf16(acc2[mt][nt][0], acc2[mt][nt][1]);
                    if (row1 < N)
                        *reinterpret_cast<uint32_t*>(PN + (size_t)row1 * L2OUT + cn) =
                            pack_bf16(acc2[mt][nt][2], acc2[mt][nt][3]);
                }
            }
        }
    }
}

// ---------------------------------------------------------------------------
// Finalize: out[i][c] = ps[batch[i]][c] + mean_j pn[neigh[batch[i]][j]][c] + b2[c]
// Lanes 0..19 each own 2 columns.
// ---------------------------------------------------------------------------
__global__ __launch_bounds__(256)
void finalize40(const float* __restrict__ ps, const bf16* __restrict__ pn,
                const int* __restrict__ neigh,
                const int* __restrict__ batch,
                const float* __restrict__ b2,
                float* __restrict__ out, int N)
{
    int w    = (blockIdx.x * blockDim.x + threadIdx.x) >> 5;
    int lane = threadIdx.x & 31;
    if (w >= N) return;
    int node  = batch[w];
    int myidx = neigh[node * DEG + lane];
    const bool active = lane < (L2OUT / 2);

    float ax = 0.f, ay = 0.f;
#pragma unroll
    for (int j = 0; j < DEG; ++j) {
        int nb = __shfl_sync(0xffffffffu, myidx, j);
        if (active) {
            uint32_t u = __ldg(reinterpret_cast<const uint32_t*>(
                                   pn + (size_t)nb * L2OUT) + lane);
            float2 v = __bfloat1622float2(*reinterpret_cast<__nv_bfloat162*>(&u));
            ax += v.x; ay += v.y;
        }
    }
    if (active) {
        const float s = 1.0f / (float)DEG;
        float2 self = *reinterpret_cast<const float2*>(
                          ps + (size_t)node * L2OUT + lane * 2);
        float2 bb = *reinterpret_cast<const float2*>(b2 + lane * 2);
        float2 o = make_float2(self.x + ax * s + bb.x,
                               self.y + ay * s + bb.y);
        *reinterpret_cast<float2*>(out + (size_t)w * L2OUT + lane * 2) = o;
    }
}

// ---------------------------------------------------------------------------
extern "C" void kernel_launch(void* const* d_in, const int* in_sizes, int n_in,
                              void* d_out, int out_size)
{
    const float* feats = (const float*)d_in[0];
    const int*   neigh = (const int*)  d_in[1];
    const int*   batch = (const int*)  d_in[2];
    const float* W1    = (const float*)d_in[3];
    const float* b1    = (const float*)d_in[4];
    const float* W2    = (const float*)d_in[5];
    const float* b2    = (const float*)d_in[6];
    float*       out   = (float*)d_out;

    const int N = in_sizes[0] / F;   // 50000
    const int B = in_sizes[2];       // = N

    bf16 *fhi, *flo, *m1hi, *m1lo, *w1hi, *w1lo, *w2hi, *w2lo, *pn;
    float *ps;
    cudaGetSymbolAddress((void**)&fhi,  g_fhi);
    cudaGetSymbolAddress((void**)&flo,  g_flo);
    cudaGetSymbolAddress((void**)&m1hi, g_m1hi);
    cudaGetSymbolAddress((void**)&m1lo, g_m1lo);
    cudaGetSymbolAddress((void**)&w1hi, g_w1hi);
    cudaGetSymbolAddress((void**)&w1lo, g_w1lo);
    cudaGetSymbolAddress((void**)&w2hi, g_w2hi);
    cudaGetSymbolAddress((void**)&w2lo, g_w2lo);
    cudaGetSymbolAddress((void**)&ps,   g_ps);
    cudaGetSymbolAddress((void**)&pn,   g_pn);

    cudaFuncSetAttribute(gemm_fused, cudaFuncAttributeMaxDynamicSharedMemorySize,
                         SM_TOT);

    const int n4 = N * F / 4;
    wprep<<<(128 * 256 + 96 * 128 + 255) / 256, 256>>>(W1, W2, w1hi, w1lo,
                                                       w2hi, w2lo);
    featprep<<<(n4 + 255) / 256, 256>>>(feats, fhi, flo, n4);
    gather_mean_bf16<<<(N * 32 + 255) / 256, 256>>>(fhi, neigh, m1hi, m1lo, N);
    gemm_fused<<<(N + 127) / 128, 512, SM_TOT>>>(fhi, flo, m1hi, m1lo,
                                                 w1hi, w1lo, w2hi, w2lo,
                                                 b1, ps, pn, N);
    finalize40<<<(B * 32 + 255) / 256, 256>>>(ps, pn, neigh, batch, b2, out, B);
}

// round 7
// speedup vs baseline: 2.5498x; 1.0311x over previous
#include <cuda_runtime.h>
#include <cuda_bf16.h>
#include <cstdint>

#define NMAX 50000
#define F 128
#define DEG 32
#define L2OUT 40

typedef __nv_bfloat16 bf16;

// Scratch (device globals — no allocation allowed).
__device__ bf16 g_fhi[NMAX * F];
__device__ bf16 g_flo[NMAX * F];
__device__ bf16 g_m1hi[NMAX * F];
__device__ bf16 g_m1lo[NMAX * F];
__device__ bf16 g_w1hi[128 * 256];        // W1^T hi  [n][k]
__device__ bf16 g_w1lo[128 * 256];
__device__ bf16 g_w2hi[96 * 128];         // W2cat^T hi [n][k] (n>=80 zero)
__device__ bf16 g_w2lo[96 * 128];
__device__ float g_ps[NMAX * L2OUT];      // self projection (fp32)
__device__ bf16  g_pn[NMAX * L2OUT];      // neighbor projection (bf16)

// ======================== helpers ======================
__device__ __forceinline__ uint32_t smem_u32(const void* p) {
    uint32_t a;
    asm("{ .reg .u64 t; cvta.to.shared.u64 t, %1; cvt.u32.u64 %0, t; }"
        : "=r"(a) : "l"(p));
    return a;
}
__device__ __forceinline__ void cp_async16(uint32_t dst, const void* src,
                                           uint32_t srcsz) {
    asm volatile("cp.async.cg.shared.global [%0], [%1], 16, %2;"
                 :: "r"(dst), "l"(src), "r"(srcsz) : "memory");
}
__device__ __forceinline__ void cp_commit() {
    asm volatile("cp.async.commit_group;" ::: "memory");
}
template <int N_>
__device__ __forceinline__ void cp_wait() {
    asm volatile("cp.async.wait_group %0;" :: "n"(N_) : "memory");
}
__device__ __forceinline__ void ldm_x4(uint32_t& r0, uint32_t& r1,
                                       uint32_t& r2, uint32_t& r3, uint32_t a) {
    asm volatile("ldmatrix.sync.aligned.m8n8.x4.shared.b16 {%0,%1,%2,%3}, [%4];"
                 : "=r"(r0), "=r"(r1), "=r"(r2), "=r"(r3) : "r"(a));
}
__device__ __forceinline__ void ldm_x2(uint32_t& r0, uint32_t& r1, uint32_t a) {
    asm volatile("ldmatrix.sync.aligned.m8n8.x2.shared.b16 {%0,%1}, [%2];"
                 : "=r"(r0), "=r"(r1) : "r"(a));
}
__device__ __forceinline__ void mma_bf16(float* c, const uint32_t* a,
                                         const uint32_t* b) {
    asm volatile(
        "mma.sync.aligned.m16n8k16.row.col.f32.bf16.bf16.f32 "
        "{%0,%1,%2,%3}, {%4,%5,%6,%7}, {%8,%9}, {%0,%1,%2,%3};"
        : "+f"(c[0]), "+f"(c[1]), "+f"(c[2]), "+f"(c[3])
        : "r"(a[0]), "r"(a[1]), "r"(a[2]), "r"(a[3]), "r"(b[0]), "r"(b[1]));
}
__device__ __forceinline__ uint32_t bf16pair(float x, float y,
                                             float& rx, float& ry) {
    bf16 hx = __float2bfloat16(x);
    bf16 hy = __float2bfloat16(y);
    rx = x - __bfloat162float(hx);
    ry = y - __bfloat162float(hy);
    return ((uint32_t)__bfloat16_as_ushort(hy) << 16) |
           (uint32_t)__bfloat16_as_ushort(hx);
}
__device__ __forceinline__ uint32_t bf16pair_lo(float rx, float ry) {
    bf16 lx = __float2bfloat16(rx);
    bf16 ly = __float2bfloat16(ry);
    return ((uint32_t)__bfloat16_as_ushort(ly) << 16) |
           (uint32_t)__bfloat16_as_ushort(lx);
}
__device__ __forceinline__ uint32_t pack_bf16(float x, float y) {
    return ((uint32_t)__bfloat16_as_ushort(__float2bfloat16(y)) << 16) |
           (uint32_t)__bfloat16_as_ushort(__float2bfloat16(x));
}

// ---------------------------------------------------------------------------
// One-time weight prep.
// ---------------------------------------------------------------------------
__global__ __launch_bounds__(256)
void wprep(const float* __restrict__ W1, const float* __restrict__ W2,
           bf16* __restrict__ w1hi, bf16* __restrict__ w1lo,
           bf16* __restrict__ w2hi, bf16* __restrict__ w2lo)
{
    int i = blockIdx.x * 256 + threadIdx.x;
    if (i < 128 * 256) {
        int n = i >> 8, k = i & 255;
        float v = W1[(size_t)k * 128 + n];
        bf16 h = __float2bfloat16(v);
        w1hi[i] = h;
        w1lo[i] = __float2bfloat16(v - __bfloat162float(h));
    } else if (i < 128 * 256 + 96 * 128) {
        int j = i - 128 * 256;
        int n = j >> 7, k = j & 127;
        float v = 0.f;
        if (n < L2OUT)          v = W2[(size_t)k * L2OUT + n];
        else if (n < 2 * L2OUT) v = W2[(size_t)(F + k) * L2OUT + (n - L2OUT)];
        bf16 h = __float2bfloat16(v);
        w2hi[j] = h;
        w2lo[j] = __float2bfloat16(v - __bfloat162float(h));
    }
}

// ---------------------------------------------------------------------------
// feats fp32 -> hi/lo bf16.
// ---------------------------------------------------------------------------
__global__ __launch_bounds__(256)
void featprep(const float* __restrict__ src, bf16* __restrict__ hi,
              bf16* __restrict__ lo, int n4)
{
    int i = blockIdx.x * 256 + threadIdx.x;
    if (i >= n4) return;
    float4 v = reinterpret_cast<const float4*>(src)[i];
    float r0, r1, r2, r3;
    uint32_t h0 = bf16pair(v.x, v.y, r0, r1);
    uint32_t h1 = bf16pair(v.z, v.w, r2, r3);
    uint32_t l0 = bf16pair_lo(r0, r1);
    uint32_t l1 = bf16pair_lo(r2, r3);
    reinterpret_cast<uint2*>(hi)[i] = make_uint2(h0, h1);
    reinterpret_cast<uint2*>(lo)[i] = make_uint2(l0, l1);
}

// ---------------------------------------------------------------------------
// Gather-mean over bf16 feats (fp32 accumulation), emit hi/lo bf16.
// ---------------------------------------------------------------------------
__global__ __launch_bounds__(256)
void gather_mean_bf16(const bf16* __restrict__ src,
                      const int* __restrict__ neigh,
                      bf16* __restrict__ dhi, bf16* __restrict__ dlo, int N)
{
    int w    = (blockIdx.x * blockDim.x + threadIdx.x) >> 5;
    int lane = threadIdx.x & 31;
    if (w >= N) return;
    int myidx = neigh[w * DEG + lane];

    float4 acc = make_float4(0.f, 0.f, 0.f, 0.f);
#pragma unroll
    for (int j = 0; j < DEG; ++j) {
        int nb = __shfl_sync(0xffffffffu, myidx, j);
        uint2 u = __ldg(reinterpret_cast<const uint2*>(src + (size_t)nb * F) + lane);
        float2 a = __bfloat1622float2(*reinterpret_cast<__nv_bfloat162*>(&u.x));
        float2 b = __bfloat1622float2(*reinterpret_cast<__nv_bfloat162*>(&u.y));
        acc.x += a.x; acc.y += a.y; acc.z += b.x; acc.w += b.y;
    }
    const float s = 1.0f / (float)DEG;
    acc.x *= s; acc.y *= s; acc.z *= s; acc.w *= s;
    float r0, r1, r2, r3;
    uint32_t h0 = bf16pair(acc.x, acc.y, r0, r1);
    uint32_t h1 = bf16pair(acc.z, acc.w, r2, r3);
    uint32_t l0 = bf16pair_lo(r0, r1);
    uint32_t l1 = bf16pair_lo(r2, r3);
    reinterpret_cast<uint2*>(dhi + (size_t)w * F)[lane] = make_uint2(h0, h1);
    reinterpret_cast<uint2*>(dlo + (size_t)w * F)[lane] = make_uint2(l0, l1);
}

// ---------------------------------------------------------------------------
// Fused GEMM, cp.async double-buffered:
//   stage 1: h1 = relu([feats | m1] @ W1 + b1)  (SMEM only)
//   stage 2: ps = h1 @ W2_self (fp32), pn = h1 @ W2_nbr (bf16)
// SMEM: buf0 [0,73728), buf1 [73728,147456): each {AHI,ALO,BHI,BLO} of
// 18432 B. W2 tiles at 147456 (2x26112). H1 hi/lo reuse buf0 for stage 2.
// ---------------------------------------------------------------------------
#define LDT  72
#define LDT2 136
#define BUFSZ   73728
#define OFF_AHI 0
#define OFF_ALO 18432
#define OFF_BHI 36864
#define OFF_BLO 55296
#define H1_HI   0
#define H1_LO   34816
#define B2_HI   147456
#define B2_LO   173568
#define SM_TOT  199680

__global__ __launch_bounds__(512, 1)
void gemm_fused(const bf16* __restrict__ fhi, const bf16* __restrict__ flo,
                const bf16* __restrict__ m1hi, const bf16* __restrict__ m1lo,
                const bf16* __restrict__ w1hi, const bf16* __restrict__ w1lo,
                const bf16* __restrict__ w2hi, const bf16* __restrict__ w2lo,
                const float* __restrict__ b1,
                float* __restrict__ PS, bf16* __restrict__ PN, int N)
{
    extern __shared__ __align__(16) char smem[];
    const uint32_t sbase = smem_u32(smem);
    const int tid   = threadIdx.x;
    const int wid   = tid >> 5;
    const int lane  = tid & 31;
    const int warpM = wid >> 2;
    const int warpN = wid & 3;
    const int rowBase = blockIdx.x * 128;

    // ---- chunk loader: issue cp.async for chunk c into buffer b ----
    auto load_chunk = [&](int c, int b) {
        const bf16* srcHi = (c < 2) ? fhi : m1hi;
        const bf16* srcLo = (c < 2) ? flo : m1lo;
        const int kOff = (c & 1) * 64;
        const uint32_t base = sbase + b * BUFSZ;
        // A tiles: 128 rows x 64 halves; 1024 16B copies per tile
#pragma unroll
        for (int i = tid; i < 1024; i += 512) {
            int row = i >> 3, h8 = i & 7;
            int grow = rowBase + row;
            uint32_t sz = (grow < N) ? 16u : 0u;
            size_t goff = (size_t)grow * F + kOff + h8 * 8;
            uint32_t o = (uint32_t)(row * LDT + h8 * 8) * 2;
            cp_async16(base + OFF_AHI + o, srcHi + goff, sz);
            cp_async16(base + OFF_ALO + o, srcLo + goff, sz);
        }
        // B tiles: W1^T rows, k slice c*64..+63
#pragma unroll
        for (int i = tid; i < 1024; i += 512) {
            int n = i >> 3, h8 = i & 7;
            size_t goff = (size_t)n * 256 + c * 64 + h8 * 8;
            uint32_t o = (uint32_t)(n * LDT + h8 * 8) * 2;
            cp_async16(base + OFF_BHI + o, w1hi + goff, 16u);
            cp_async16(base + OFF_BLO + o, w1lo + goff, 16u);
        }
    };

    // ---- prologue: chunk 0 in flight, then W2 tiles (regular copies) ----
    load_chunk(0, 0);
    cp_commit();
#pragma unroll
    for (int i = tid; i < 1536; i += 512) {
        int n = i >> 4, h8 = i & 15;
        uint4 vh = *reinterpret_cast<const uint4*>(w2hi + n * 128 + h8 * 8);
        uint4 vl = *reinterpret_cast<const uint4*>(w2lo + n * 128 + h8 * 8);
        uint32_t o = (uint32_t)(n * LDT2 + h8 * 8) * 2;
        *reinterpret_cast<uint4*>(smem + B2_HI + o) = vh;
        *reinterpret_cast<uint4*>(smem + B2_LO + o) = vl;
    }

    // ldmatrix address components
    const uint32_t aRowSel = lane & 15;
    const uint32_t aKoff   = (uint32_t)(lane >> 4) << 3;
    const uint32_t bRowSel = lane & 7;
    const uint32_t bKoff   = (uint32_t)((lane >> 3) & 1) << 3;
    const uint32_t aOffHi = ((warpM * 32 + aRowSel) * LDT + aKoff) * 2;
    const uint32_t bOffHi = ((warpN * 32 + bRowSel) * LDT + bKoff) * 2;

    float acc[2][4][4];
#pragma unroll
    for (int mt = 0; mt < 2; ++mt)
#pragma unroll
        for (int nt = 0; nt < 4; ++nt)
#pragma unroll
            for (int q = 0; q < 4; ++q) acc[mt][nt][q] = 0.f;

    // ======================= STAGE 1 (pipelined) =======================
    for (int c = 0; c < 4; ++c) {
        if (c < 3) {
            load_chunk(c + 1, (c + 1) & 1);
            cp_commit();
        }
        if (c < 3) cp_wait<1>(); else cp_wait<0>();
        __syncthreads();

        const uint32_t base = sbase + (c & 1) * BUFSZ;
#pragma unroll
        for (int ks = 0; ks < 4; ++ks) {
            const uint32_t k2 = ks * 32;
            uint32_t ahi[2][4], alo[2][4], bhi[4][2], blo[4][2];
#pragma unroll
            for (int mt = 0; mt < 2; ++mt) {
                uint32_t ao = base + aOffHi + mt * (16 * LDT * 2) + k2;
                ldm_x4(ahi[mt][0], ahi[mt][1], ahi[mt][2], ahi[mt][3],
                       ao + OFF_AHI);
                ldm_x4(alo[mt][0], alo[mt][1], alo[mt][2], alo[mt][3],
                       ao + OFF_ALO);
            }
#pragma unroll
            for (int nt = 0; nt < 4; ++nt) {
                uint32_t bo = base + bOffHi + nt * (8 * LDT * 2) + k2;
                ldm_x2(bhi[nt][0], bhi[nt][1], bo + OFF_BHI);
                ldm_x2(blo[nt][0], blo[nt][1], bo + OFF_BLO);
            }
#pragma unroll
            for (int mt = 0; mt < 2; ++mt)
#pragma unroll
                for (int nt = 0; nt < 4; ++nt) {
                    mma_bf16(acc[mt][nt], ahi[mt], bhi[nt]);
                    mma_bf16(acc[mt][nt], ahi[mt], blo[nt]);
                    mma_bf16(acc[mt][nt], alo[mt], bhi[nt]);
                }
        }
        __syncthreads();   // protect this buffer before reuse at c+2
    }

    // bias + relu -> h1 hi/lo into buf0 region
    {
        const int g  = lane >> 2;
        const int qc = (lane & 3) * 2;
#pragma unroll
        for (int mt = 0; mt < 2; ++mt) {
#pragma unroll
            for (int nt = 0; nt < 4; ++nt) {
                int col = warpN * 32 + nt * 8 + qc;
                float bx = b1[col], by = b1[col + 1];
                int rl0 = warpM * 32 + mt * 16 + g;
                int rl1 = rl0 + 8;
                float v0 = fmaxf(acc[mt][nt][0] + bx, 0.f);
                float v1 = fmaxf(acc[mt][nt][1] + by, 0.f);
                float v2 = fmaxf(acc[mt][nt][2] + bx, 0.f);
                float v3 = fmaxf(acc[mt][nt][3] + by, 0.f);
                float rx, ry;
                uint32_t hi0 = bf16pair(v0, v1, rx, ry);
                uint32_t lo0 = bf16pair_lo(rx, ry);
                uint32_t o0 = (uint32_t)(rl0 * LDT2 + col) * 2;
                uint32_t hi1 = bf16pair(v2, v3, rx, ry);
                uint32_t lo1 = bf16pair_lo(rx, ry);
                uint32_t o1 = (uint32_t)(rl1 * LDT2 + col) * 2;
                *reinterpret_cast<uint32_t*>(smem + H1_HI + o0) = hi0;
                *reinterpret_cast<uint32_t*>(smem + H1_LO + o0) = lo0;
                *reinterpret_cast<uint32_t*>(smem + H1_HI + o1) = hi1;
                *reinterpret_cast<uint32_t*>(smem + H1_LO + o1) = lo1;
            }
        }
    }
    __syncthreads();

    // ======================= STAGE 2 =======================
    uint32_t a2Hi[2], a2Lo[2], b2Hi[3], b2Lo[3];
#pragma unroll
    for (int mt = 0; mt < 2; ++mt) {
        uint32_t off = ((warpM * 32 + mt * 16 + aRowSel) * LDT2 + aKoff) * 2;
        a2Hi[mt] = sbase + H1_HI + off;
        a2Lo[mt] = sbase + H1_LO + off;
    }
#pragma unroll
    for (int nt = 0; nt < 3; ++nt) {
        uint32_t off = ((warpN * 24 + nt * 8 + bRowSel) * LDT2 + bKoff) * 2;
        b2Hi[nt] = sbase + B2_HI + off;
        b2Lo[nt] = sbase + B2_LO + off;
    }

    float acc2[2][3][4];
#pragma unroll
    for (int mt = 0; mt < 2; ++mt)
#pragma unroll
        for (int nt = 0; nt < 3; ++nt)
#pragma unroll
            for (int q = 0; q < 4; ++q) acc2[mt][nt][q] = 0.f;

#pragma unroll
    for (int ks = 0; ks < 8; ++ks) {
        const uint32_t k2 = ks * 32;
        uint32_t ahi[2][4], alo[2][4], bhi[3][2], blo[3][2];
#pragma unroll
        for (int mt = 0; mt < 2; ++mt) {
            ldm_x4(ahi[mt][0], ahi[mt][1], ahi[mt][2], ahi[mt][3], a2Hi[mt] + k2);
            ldm_x4(alo[mt][0], alo[mt][1], alo[mt][2], alo[mt][3], a2Lo[mt] + k2);
        }
#pragma unroll
        for (int nt = 0; nt < 3; ++nt) {
            ldm_x2(bhi[nt][0], bhi[nt][1], b2Hi[nt] + k2);
            ldm_x2(blo[nt][0], blo[nt][1], b2Lo[nt] + k2);
        }
#pragma unroll
        for (int mt = 0; mt < 2; ++mt)
#pragma unroll
            for (int nt = 0; nt < 3; ++nt) {
                mma_bf16(acc2[mt][nt], ahi[mt], bhi[nt]);
                mma_bf16(acc2[mt][nt], ahi[mt], blo[nt]);
                mma_bf16(acc2[mt][nt], alo[mt], bhi[nt]);
            }
    }

    // Store: cols 0..39 -> PS (fp32), 40..79 -> PN (bf16), 80..95 dropped
    {
        const int g  = lane >> 2;
        const int qc = (lane & 3) * 2;
#pragma unroll
        for (int mt = 0; mt < 2; ++mt) {
#pragma unroll
            for (int nt = 0; nt < 3; ++nt) {
                int col = warpN * 24 + nt * 8 + qc;
                if (col >= 2 * L2OUT) continue;
                int row0 = rowBase + warpM * 32 + mt * 16 + g;
                int row1 = row0 + 8;
                if (col < L2OUT) {
                    if (row0 < N)
                        *reinterpret_cast<float2*>(&PS[(size_t)row0 * L2OUT + col]) =
                            make_float2(acc2[mt][nt][0], acc2[mt][nt][1]);
                    if (row1 < N)
                        *reinterpret_cast<float2*>(&PS[(size_t)row1 * L2OUT + col]) =
                            make_float2(acc2[mt][nt][2], acc2[mt][nt][3]);
                } else {
                    int cn = col - L2OUT;
                    if (row0 < N)
                        *reinterpret_cast<uint32_t*>(PN + (size_t)row0 * L2OUT + cn) =
                            pack_bf16(acc2[mt][nt][0], acc2[mt][nt][1]);
                    if (row1 < N)
                        *reinterpret_cast<uint32_t*>(PN + (size_t)row1 * L2OUT + cn) =
                            pack_bf16(acc2[mt][nt][2], acc2[mt][nt][3]);
                }
            }
        }
    }
}

// ---------------------------------------------------------------------------
// Finalize: out[i][c] = ps[batch[i]][c] + mean_j pn[neigh[batch[i]][j]][c] + b2[c]
// ---------------------------------------------------------------------------
__global__ __launch_bounds__(256)
void finalize40(const float* __restrict__ ps, const bf16* __restrict__ pn,
                const int* __restrict__ neigh,
                const int* __restrict__ batch,
                const float* __restrict__ b2,
                float* __restrict__ out, int N)
{
    int w    = (blockIdx.x * blockDim.x + threadIdx.x) >> 5;
    int lane = threadIdx.x & 31;
    if (w >= N) return;
    int node  = batch[w];
    int myidx = neigh[node * DEG + lane];
    const bool active = lane < (L2OUT / 2);

    float ax = 0.f, ay = 0.f;
#pragma unroll
    for (int j = 0; j < DEG; ++j) {
        int nb = __shfl_sync(0xffffffffu, myidx, j);
        if (active) {
            uint32_t u = __ldg(reinterpret_cast<const uint32_t*>(
                                   pn + (size_t)nb * L2OUT) + lane);
            float2 v = __bfloat1622float2(*reinterpret_cast<__nv_bfloat162*>(&u));
            ax += v.x; ay += v.y;
        }
    }
    if (active) {
        const float s = 1.0f / (float)DEG;
        float2 self = *reinterpret_cast<const float2*>(
                          ps + (size_t)node * L2OUT + lane * 2);
        float2 bb = *reinterpret_cast<const float2*>(b2 + lane * 2);
        float2 o = make_float2(self.x + ax * s + bb.x,
                               self.y + ay * s + bb.y);
        *reinterpret_cast<float2*>(out + (size_t)w * L2OUT + lane * 2) = o;
    }
}

// ---------------------------------------------------------------------------
extern "C" void kernel_launch(void* const* d_in, const int* in_sizes, int n_in,
                              void* d_out, int out_size)
{
    const float* feats = (const float*)d_in[0];
    const int*   neigh = (const int*)  d_in[1];
    const int*   batch = (const int*)  d_in[2];
    const float* W1    = (const float*)d_in[3];
    const float* b1    = (const float*)d_in[4];
    const float* W2    = (const float*)d_in[5];
    const float* b2    = (const float*)d_in[6];
    float*       out   = (float*)d_out;

    const int N = in_sizes[0] / F;   // 50000
    const int B = in_sizes[2];       // = N

    bf16 *fhi, *flo, *m1hi, *m1lo, *w1hi, *w1lo, *w2hi, *w2lo, *pn;
    float *ps;
    cudaGetSymbolAddress((void**)&fhi,  g_fhi);
    cudaGetSymbolAddress((void**)&flo,  g_flo);
    cudaGetSymbolAddress((void**)&m1hi, g_m1hi);
    cudaGetSymbolAddress((void**)&m1lo, g_m1lo);
    cudaGetSymbolAddress((void**)&w1hi, g_w1hi);
    cudaGetSymbolAddress((void**)&w1lo, g_w1lo);
    cudaGetSymbolAddress((void**)&w2hi, g_w2hi);
    cudaGetSymbolAddress((void**)&w2lo, g_w2lo);
    cudaGetSymbolAddress((void**)&ps,   g_ps);
    cudaGetSymbolAddress((void**)&pn,   g_pn);

    cudaFuncSetAttribute(gemm_fused, cudaFuncAttributeMaxDynamicSharedMemorySize,
                         SM_TOT);

    const int n4 = N * F / 4;
    wprep<<<(128 * 256 + 96 * 128 + 255) / 256, 256>>>(W1, W2, w1hi, w1lo,
                                                       w2hi, w2lo);
    featprep<<<(n4 + 255) / 256, 256>>>(feats, fhi, flo, n4);
    gather_mean_bf16<<<(N * 32 + 255) / 256, 256>>>(fhi, neigh, m1hi, m1lo, N);
    gemm_fused<<<(N + 127) / 128, 512, SM_TOT>>>(fhi, flo, m1hi, m1lo,
                                                 w1hi, w1lo, w2hi, w2lo,
                                                 b1, ps, pn, N);
    finalize40<<<(B * 32 + 255) / 256, 256>>>(ps, pn, neigh, batch, b2, out, B);
}

// round 9
// speedup vs baseline: 2.7719x; 1.0871x over previous
#include <cuda_runtime.h>
#include <cuda_bf16.h>
#include <cstdint>

#define NMAX 50000
#define F 128
#define DEG 32
#define L2OUT 40

typedef __nv_bfloat16 bf16;

// Scratch (device globals — no allocation allowed).
__device__ bf16 g_fhi[NMAX * F];          // feats hi
__device__ bf16 g_flo[NMAX * F];          // feats lo (residual)
__device__ bf16 g_m1hi[NMAX * F];         // neighbor-mean (hi only)
__device__ bf16 g_w1hi[128 * 256];        // W1^T hi  [n][k]
__device__ bf16 g_w1lo[128 * 256];        // W1^T lo
__device__ bf16 g_w2hi[96 * 128];         // W2cat^T hi [n][k] (n>=80 zero)
__device__ bf16 g_w2lo[96 * 128];
__device__ float g_ps[NMAX * L2OUT];      // self projection (fp32)
__device__ bf16  g_pn[NMAX * L2OUT];      // neighbor projection (bf16)

// ======================== helpers ======================
__device__ __forceinline__ uint32_t smem_u32(const void* p) {
    uint32_t a;
    asm("{ .reg .u64 t; cvta.to.shared.u64 t, %1; cvt.u32.u64 %0, t; }"
        : "=r"(a) : "l"(p));
    return a;
}
__device__ __forceinline__ void cp_async16(uint32_t dst, const void* src,
                                           uint32_t srcsz) {
    asm volatile("cp.async.cg.shared.global [%0], [%1], 16, %2;"
                 :: "r"(dst), "l"(src), "r"(srcsz) : "memory");
}
__device__ __forceinline__ void cp_commit() {
    asm volatile("cp.async.commit_group;" ::: "memory");
}
template <int N_>
__device__ __forceinline__ void cp_wait() {
    asm volatile("cp.async.wait_group %0;" :: "n"(N_) : "memory");
}
__device__ __forceinline__ void ldm_x4(uint32_t& r0, uint32_t& r1,
                                       uint32_t& r2, uint32_t& r3, uint32_t a) {
    asm volatile("ldmatrix.sync.aligned.m8n8.x4.shared.b16 {%0,%1,%2,%3}, [%4];"
                 : "=r"(r0), "=r"(r1), "=r"(r2), "=r"(r3) : "r"(a));
}
__device__ __forceinline__ void mma_bf16(float* c, const uint32_t* a,
                                         const uint32_t* b) {
    asm volatile(
        "mma.sync.aligned.m16n8k16.row.col.f32.bf16.bf16.f32 "
        "{%0,%1,%2,%3}, {%4,%5,%6,%7}, {%8,%9}, {%0,%1,%2,%3};"
        : "+f"(c[0]), "+f"(c[1]), "+f"(c[2]), "+f"(c[3])
        : "r"(a[0]), "r"(a[1]), "r"(a[2]), "r"(a[3]), "r"(b[0]), "r"(b[1]));
}
__device__ __forceinline__ uint32_t bf16pair(float x, float y,
                                             float& rx, float& ry) {
    bf16 hx = __float2bfloat16(x);
    bf16 hy = __float2bfloat16(y);
    rx = x - __bfloat162float(hx);
    ry = y - __bfloat162float(hy);
    return ((uint32_t)__bfloat16_as_ushort(hy) << 16) |
           (uint32_t)__bfloat16_as_ushort(hx);
}
__device__ __forceinline__ uint32_t bf16pair_lo(float rx, float ry) {
    bf16 lx = __float2bfloat16(rx);
    bf16 ly = __float2bfloat16(ry);
    return ((uint32_t)__bfloat16_as_ushort(ly) << 16) |
           (uint32_t)__bfloat16_as_ushort(lx);
}
__device__ __forceinline__ uint32_t pack_bf16(float x, float y) {
    return ((uint32_t)__bfloat16_as_ushort(__float2bfloat16(y)) << 16) |
           (uint32_t)__bfloat16_as_ushort(__float2bfloat16(x));
}

// ---------------------------------------------------------------------------
// One-time weight prep.
// ---------------------------------------------------------------------------
__global__ __launch_bounds__(256)
void wprep(const float* __restrict__ W1, const float* __restrict__ W2,
           bf16* __restrict__ w1hi, bf16* __restrict__ w1lo,
           bf16* __restrict__ w2hi, bf16* __restrict__ w2lo)
{
    int i = blockIdx.x * 256 + threadIdx.x;
    if (i < 128 * 256) {
        int n = i >> 8, k = i & 255;
        float v = W1[(size_t)k * 128 + n];
        bf16 h = __float2bfloat16(v);
        w1hi[i] = h;
        w1lo[i] = __float2bfloat16(v - __bfloat162float(h));
    } else if (i < 128 * 256 + 96 * 128) {
        int j = i - 128 * 256;
        int n = j >> 7, k = j & 127;
        float v = 0.f;
        if (n < L2OUT)          v = W2[(size_t)k * L2OUT + n];
        else if (n < 2 * L2OUT) v = W2[(size_t)(F + k) * L2OUT + (n - L2OUT)];
        bf16 h = __float2bfloat16(v);
        w2hi[j] = h;
        w2lo[j] = __float2bfloat16(v - __bfloat162float(h));
    }
}

// ---------------------------------------------------------------------------
// feats fp32 -> hi/lo bf16.
// ---------------------------------------------------------------------------
__global__ __launch_bounds__(256)
void featprep(const float* __restrict__ src, bf16* __restrict__ hi,
              bf16* __restrict__ lo, int n4)
{
    int i = blockIdx.x * 256 + threadIdx.x;
    if (i >= n4) return;
    float4 v = reinterpret_cast<const float4*>(src)[i];
    float r0, r1, r2, r3;
    uint32_t h0 = bf16pair(v.x, v.y, r0, r1);
    uint32_t h1 = bf16pair(v.z, v.w, r2, r3);
    uint32_t l0 = bf16pair_lo(r0, r1);
    uint32_t l1 = bf16pair_lo(r2, r3);
    reinterpret_cast<uint2*>(hi)[i] = make_uint2(h0, h1);
    reinterpret_cast<uint2*>(lo)[i] = make_uint2(l0, l1);
}

// ---------------------------------------------------------------------------
// Gather-mean over bf16 feats (fp32 accumulation), emit bf16 (hi only).
// ---------------------------------------------------------------------------
__global__ __launch_bounds__(256)
void gather_mean_bf16(const bf16* __restrict__ src,
                      const int* __restrict__ neigh,
                      bf16* __restrict__ dhi, int N)
{
    int w    = (blockIdx.x * blockDim.x + threadIdx.x) >> 5;
    int lane = threadIdx.x & 31;
    if (w >= N) return;
    int myidx = neigh[w * DEG + lane];

    float4 acc = make_float4(0.f, 0.f, 0.f, 0.f);
#pragma unroll
    for (int j = 0; j < DEG; ++j) {
        int nb = __shfl_sync(0xffffffffu, myidx, j);
        uint2 u = __ldg(reinterpret_cast<const uint2*>(src + (size_t)nb * F) + lane);
        float2 a = __bfloat1622float2(*reinterpret_cast<__nv_bfloat162*>(&u.x));
        float2 b = __bfloat1622float2(*reinterpret_cast<__nv_bfloat162*>(&u.y));
        acc.x += a.x; acc.y += a.y; acc.z += b.x; acc.w += b.y;
    }
    const float s = 1.0f / (float)DEG;
    uint32_t h0 = pack_bf16(acc.x * s, acc.y * s);
    uint32_t h1 = pack_bf16(acc.z * s, acc.w * s);
    reinterpret_cast<uint2*>(dhi + (size_t)w * F)[lane] = make_uint2(h0, h1);
}

// ---------------------------------------------------------------------------
// Fused GEMM, cp.async double-buffered, x4-LDSM B fragments:
//   stage 1: c<2 (feats): ahi*(bhi+blo) + alo*bhi   (3 products)
//            c>=2 (m1):   ahi*(bhi+blo)             (2 products)
//   stage 2: (h1hi+h1lo)*(W2hi+W2lo)                (3 products)
// ---------------------------------------------------------------------------
#define LDT  72
#define LDT2 136
#define BUFSZ   73728
#define OFF_AHI 0
#define OFF_ALO 18432
#define OFF_BHI 36864
#define OFF_BLO 55296
#define H1_HI   0
#define H1_LO   34816
#define B2_HI   147456
#define B2_LO   173568
#define SM_TOT  199680

__global__ __launch_bounds__(512, 1)
void gemm_fused(const bf16* __restrict__ fhi, const bf16* __restrict__ flo,
                const bf16* __restrict__ m1hi,
                const bf16* __restrict__ w1hi, const bf16* __restrict__ w1lo,
                const bf16* __restrict__ w2hi, const bf16* __restrict__ w2lo,
                const float* __restrict__ b1,
                float* __restrict__ PS, bf16* __restrict__ PN, int N)
{
    extern __shared__ __align__(16) char smem[];
    const uint32_t sbase = smem_u32(smem);
    const int tid   = threadIdx.x;
    const int wid   = tid >> 5;
    const int lane  = tid & 31;
    const int warpM = wid >> 2;
    const int warpN = wid & 3;
    const int rowBase = blockIdx.x * 128;

    // ---- chunk loader ----
    auto load_chunk = [&](int c, int b) {
        const bool isF = (c < 2);
        const bf16* srcHi = isF ? fhi : m1hi;
        const int kOff = (c & 1) * 64;
        const uint32_t base = sbase + b * BUFSZ;
#pragma unroll
        for (int i = tid; i < 1024; i += 512) {
            int row = i >> 3, h8 = i & 7;
            int grow = rowBase + row;
            uint32_t sz = (grow < N) ? 16u : 0u;
            size_t goff = (size_t)grow * F + kOff + h8 * 8;
            uint32_t o = (uint32_t)(row * LDT + h8 * 8) * 2;
            cp_async16(base + OFF_AHI + o, srcHi + goff, sz);
            if (isF) cp_async16(base + OFF_ALO + o, flo + goff, sz);
        }
#pragma unroll
        for (int i = tid; i < 1024; i += 512) {
            int n = i >> 3, h8 = i & 7;
            size_t goff = (size_t)n * 256 + c * 64 + h8 * 8;
            uint32_t o = (uint32_t)(n * LDT + h8 * 8) * 2;
            cp_async16(base + OFF_BHI + o, w1hi + goff, 16u);
            cp_async16(base + OFF_BLO + o, w1lo + goff, 16u);
        }
    };

    load_chunk(0, 0);
    cp_commit();
    // W2 tiles (persistent)
#pragma unroll
    for (int i = tid; i < 1536; i += 512) {
        int n = i >> 4, h8 = i & 15;
        uint4 vh = *reinterpret_cast<const uint4*>(w2hi + n * 128 + h8 * 8);
        uint4 vl = *reinterpret_cast<const uint4*>(w2lo + n * 128 + h8 * 8);
        uint32_t o = (uint32_t)(n * LDT2 + h8 * 8) * 2;
        *reinterpret_cast<uint4*>(smem + B2_HI + o) = vh;
        *reinterpret_cast<uint4*>(smem + B2_LO + o) = vl;
    }

    // ldmatrix lane-address components
    const uint32_t aRowSel = lane & 15;
    const uint32_t aKoff   = (uint32_t)(lane >> 4) << 3;       // x4 A: one k16
    const uint32_t bRowSel = lane & 7;
    const uint32_t bKoff4  = (uint32_t)((lane >> 3) & 3) << 3; // x4 B: two k16
    const uint32_t aOff  = ((warpM * 32 + aRowSel) * LDT + aKoff) * 2;
    const uint32_t bOff4 = ((warpN * 32 + bRowSel) * LDT + bKoff4) * 2;

    float acc[2][4][4];
#pragma unroll
    for (int mt = 0; mt < 2; ++mt)
#pragma unroll
        for (int nt = 0; nt < 4; ++nt)
#pragma unroll
            for (int q = 0; q < 4; ++q) acc[mt][nt][q] = 0.f;

    // ======================= STAGE 1 (pipelined) =======================
#pragma unroll
    for (int c = 0; c < 4; ++c) {
        if (c < 3) {
            load_chunk(c + 1, (c + 1) & 1);
            cp_commit();
        }
        if (c < 3) cp_wait<1>(); else cp_wait<0>();
        __syncthreads();

        const uint32_t base = sbase + (c & 1) * BUFSZ;
        const bool useLo = (c < 2);
#pragma unroll
        for (int ks2 = 0; ks2 < 2; ++ks2) {
            // B fragments for TWO k-steps per ldmatrix.x4
            uint32_t bhi[4][4], blo[4][4];
#pragma unroll
            for (int nt = 0; nt < 4; ++nt) {
                uint32_t bo = base + bOff4 + nt * (8 * LDT * 2) + ks2 * 64;
                ldm_x4(bhi[nt][0], bhi[nt][1], bhi[nt][2], bhi[nt][3],
                       bo + OFF_BHI);
                ldm_x4(blo[nt][0], blo[nt][1], blo[nt][2], blo[nt][3],
                       bo + OFF_BLO);
            }
#pragma unroll
            for (int sub = 0; sub < 2; ++sub) {
                const uint32_t k2 = (ks2 * 2 + sub) * 32;
                uint32_t ahi[2][4], alo[2][4];
#pragma unroll
                for (int mt = 0; mt < 2; ++mt) {
                    uint32_t ao = base + aOff + mt * (16 * LDT * 2) + k2;
                    ldm_x4(ahi[mt][0], ahi[mt][1], ahi[mt][2], ahi[mt][3],
                           ao + OFF_AHI);
                    if (useLo)
                        ldm_x4(alo[mt][0], alo[mt][1], alo[mt][2], alo[mt][3],
                               ao + OFF_ALO);
                }
#pragma unroll
                for (int mt = 0; mt < 2; ++mt)
#pragma unroll
                    for (int nt = 0; nt < 4; ++nt) {
                        mma_bf16(acc[mt][nt], ahi[mt], &bhi[nt][sub * 2]);
                        mma_bf16(acc[mt][nt], ahi[mt], &blo[nt][sub * 2]);
                        if (useLo)
                            mma_bf16(acc[mt][nt], alo[mt], &bhi[nt][sub * 2]);
                    }
            }
        }
        __syncthreads();
    }

    // bias + relu -> h1 hi/lo into buf0 region
    {
        const int g  = lane >> 2;
        const int qc = (lane & 3) * 2;
#pragma unroll
        for (int mt = 0; mt < 2; ++mt) {
#pragma unroll
            for (int nt = 0; nt < 4; ++nt) {
                int col = warpN * 32 + nt * 8 + qc;
                float bx = b1[col], by = b1[col + 1];
                int rl0 = warpM * 32 + mt * 16 + g;
                int rl1 = rl0 + 8;
                float v0 = fmaxf(acc[mt][nt][0] + bx, 0.f);
                float v1 = fmaxf(acc[mt][nt][1] + by, 0.f);
                float v2 = fmaxf(acc[mt][nt][2] + bx, 0.f);
                float v3 = fmaxf(acc[mt][nt][3] + by, 0.f);
                float rx, ry;
                uint32_t hi0 = bf16pair(v0, v1, rx, ry);
                uint32_t lo0 = bf16pair_lo(rx, ry);
                uint32_t o0 = (uint32_t)(rl0 * LDT2 + col) * 2;
                uint32_t hi1 = bf16pair(v2, v3, rx, ry);
                uint32_t lo1 = bf16pair_lo(rx, ry);
                uint32_t o1 = (uint32_t)(rl1 * LDT2 + col) * 2;
                *reinterpret_cast<uint32_t*>(smem + H1_HI + o0) = hi0;
                *reinterpret_cast<uint32_t*>(smem + H1_LO + o0) = lo0;
                *reinterpret_cast<uint32_t*>(smem + H1_HI + o1) = hi1;
                *reinterpret_cast<uint32_t*>(smem + H1_LO + o1) = lo1;
            }
        }
    }
    __syncthreads();

    // ======================= STAGE 2 =======================
    const uint32_t a2Off  = ((warpM * 32 + aRowSel) * LDT2 + aKoff) * 2;
    const uint32_t b2Off4 = ((warpN * 24 + bRowSel) * LDT2 + bKoff4) * 2;

    float acc2[2][3][4];
#pragma unroll
    for (int mt = 0; mt < 2; ++mt)
#pragma unroll
        for (int nt = 0; nt < 3; ++nt)
#pragma unroll
            for (int q = 0; q < 4; ++q) acc2[mt][nt][q] = 0.f;

#pragma unroll
    for (int ks2 = 0; ks2 < 4; ++ks2) {
        uint32_t bhi[3][4], blo[3][4];
#pragma unroll
        for (int nt = 0; nt < 3; ++nt) {
            uint32_t bo = sbase + b2Off4 + nt * (8 * LDT2 * 2) + ks2 * 64;
            ldm_x4(bhi[nt][0], bhi[nt][1], bhi[nt][2], bhi[nt][3], bo + B2_HI);
            ldm_x4(blo[nt][0], blo[nt][1], blo[nt][2], blo[nt][3], bo + B2_LO);
        }
#pragma unroll
        for (int sub = 0; sub < 2; ++sub) {
            const uint32_t k2 = (ks2 * 2 + sub) * 32;
            uint32_t ahi[2][4], alo[2][4];
#pragma unroll
            for (int mt = 0; mt < 2; ++mt) {
                uint32_t ao = sbase + a2Off + mt * (16 * LDT2 * 2) + k2;
                ldm_x4(ahi[mt][0], ahi[mt][1], ahi[mt][2], ahi[mt][3],
                       ao + H1_HI);
                ldm_x4(alo[mt][0], alo[mt][1], alo[mt][2], alo[mt][3],
                       ao + H1_LO);
            }
#pragma unroll
            for (int mt = 0; mt < 2; ++mt)
#pragma unroll
                for (int nt = 0; nt < 3; ++nt) {
                    mma_bf16(acc2[mt][nt], ahi[mt], &bhi[nt][sub * 2]);
                    mma_bf16(acc2[mt][nt], ahi[mt], &blo[nt][sub * 2]);
                    mma_bf16(acc2[mt][nt], alo[mt], &bhi[nt][sub * 2]);
                }
        }
    }

    // Store: cols 0..39 -> PS (fp32), 40..79 -> PN (bf16), 80..95 dropped
    {
        const int g  = lane >> 2;
        const int qc = (lane & 3) * 2;
#pragma unroll
        for (int mt = 0; mt < 2; ++mt) {
#pragma unroll
            for (int nt = 0; nt < 3; ++nt) {
                int col = warpN * 24 + nt * 8 + qc;
                if (col >= 2 * L2OUT) continue;
                int row0 = rowBase + warpM * 32 + mt * 16 + g;
                int row1 = row0 + 8;
                if (col < L2OUT) {
                    if (row0 < N)
                        *reinterpret_cast<float2*>(&PS[(size_t)row0 * L2OUT + col]) =
                            make_float2(acc2[mt][nt][0], acc2[mt][nt][1]);
                    if (row1 < N)
                        *reinterpret_cast<float2*>(&PS[(size_t)row1 * L2OUT + col]) =
                            make_float2(acc2[mt][nt][2], acc2[mt][nt][3]);
                } else {
                    int cn = col - L2OUT;
                    if (row0 < N)
                        *reinterpret_cast<uint32_t*>(PN + (size_t)row0 * L2OUT + cn) =
                            pack_bf16(acc2[mt][nt][0], acc2[mt][nt][1]);
                    if (row1 < N)
                        *reinterpret_cast<uint32_t*>(PN + (size_t)row1 * L2OUT + cn) =
                            pack_bf16(acc2[mt][nt][2], acc2[mt][nt][3]);
                }
            }
        }
    }
}

// ---------------------------------------------------------------------------
// Finalize: out[i][c] = ps[batch[i]][c] + mean_j pn[neigh[batch[i]][j]][c] + b2[c]
// ---------------------------------------------------------------------------
__global__ __launch_bounds__(256)
void finalize40(const float* __restrict__ ps, const bf16* __restrict__ pn,
                const int* __restrict__ neigh,
                const int* __restrict__ batch,
                const float* __restrict__ b2,
                float* __restrict__ out, int N)
{
    int w    = (blockIdx.x * blockDim.x + threadIdx.x) >> 5;
    int lane = threadIdx.x & 31;
    if (w >= N) return;
    int node  = batch[w];
    int myidx = neigh[node * DEG + lane];
    const bool active = lane < (L2OUT / 2);

    float ax = 0.f, ay = 0.f;
#pragma unroll
    for (int j = 0; j < DEG; ++j) {
        int nb = __shfl_sync(0xffffffffu, myidx, j);
        if (active) {
            uint32_t u = __ldg(reinterpret_cast<const uint32_t*>(
                                   pn + (size_t)nb * L2OUT) + lane);
            float2 v = __bfloat1622float2(*reinterpret_cast<__nv_bfloat162*>(&u));
            ax += v.x; ay += v.y;
        }
    }
    if (active) {
        const float s = 1.0f / (float)DEG;
        float2 self = *reinterpret_cast<const float2*>(
                          ps + (size_t)node * L2OUT + lane * 2);
        float2 bb = *reinterpret_cast<const float2*>(b2 + lane * 2);
        float2 o = make_float2(self.x + ax * s + bb.x,
                               self.y + ay * s + bb.y);
        *reinterpret_cast<float2*>(out + (size_t)w * L2OUT + lane * 2) = o;
    }
}

// ---------------------------------------------------------------------------
extern "C" void kernel_launch(void* const* d_in, const int* in_sizes, int n_in,
                              void* d_out, int out_size)
{
    const float* feats = (const float*)d_in[0];
    const int*   neigh = (const int*)  d_in[1];
    const int*   batch = (const int*)  d_in[2];
    const float* W1    = (const float*)d_in[3];
    const float* b1    = (const float*)d_in[4];
    const float* W2    = (const float*)d_in[5];
    const float* b2    = (const float*)d_in[6];
    float*       out   = (float*)d_out;

    const int N = in_sizes[0] / F;   // 50000
    const int B = in_sizes[2];       // = N

    bf16 *fhi, *flo, *m1hi, *w1hi, *w1lo, *w2hi, *w2lo, *pn;
    float *ps;
    cudaGetSymbolAddress((void**)&fhi,  g_fhi);
    cudaGetSymbolAddress((void**)&flo,  g_flo);
    cudaGetSymbolAddress((void**)&m1hi, g_m1hi);
    cudaGetSymbolAddress((void**)&w1hi, g_w1hi);
    cudaGetSymbolAddress((void**)&w1lo, g_w1lo);
    cudaGetSymbolAddress((void**)&w2hi, g_w2hi);
    cudaGetSymbolAddress((void**)&w2lo, g_w2lo);
    cudaGetSymbolAddress((void**)&ps,   g_ps);
    cudaGetSymbolAddress((void**)&pn,   g_pn);

    cudaFuncSetAttribute(gemm_fused, cudaFuncAttributeMaxDynamicSharedMemorySize,
                         SM_TOT);

    const int n4 = N * F / 4;
    wprep<<<(128 * 256 + 96 * 128 + 255) / 256, 256>>>(W1, W2, w1hi, w1lo,
                                                       w2hi, w2lo);
    featprep<<<(n4 + 255) / 256, 256>>>(feats, fhi, flo, n4);
    gather_mean_bf16<<<(N * 32 + 255) / 256, 256>>>(fhi, neigh, m1hi, N);
    gemm_fused<<<(N + 127) / 128, 512, SM_TOT>>>(fhi, flo, m1hi, w1hi, w1lo,
                                                 w2hi, w2lo, b1, ps, pn, N);
    finalize40<<<(B * 32 + 255) / 256, 256>>>(ps, pn, neigh, batch, b2, out, B);
}